// round 10
// baseline (speedup 1.0000x reference)
#include <cuda_runtime.h>
#include <cuda_fp16.h>
#include <math.h>
#include <stdint.h>

#define N_NODES 50000
#define N_EDGES 320000
#define D       128
#define HID     512
#define KN      256
#define KE      384
#define EPSV    1e-5f
#define STAT_BLOCKS 256

// ---------------- device scratch (allocation-free: static globals) ----------
__device__ float  g_msg[(size_t)N_NODES * D];           // fp32 scatter target
__device__ __half g_H[(size_t)N_EDGES * HID];           // hidden acts fp16
__device__ __half g_W1hT[(size_t)HID * KE];             // folded W1 [n][k] fp16
__device__ __half g_W2h[(size_t)D * HID];               // W2 [n][k] fp16
__device__ __half g_nodes_h[(size_t)N_NODES * D];       // fp16 mirrors
__device__ __half g_msg_h[(size_t)N_NODES * D];
__device__ __half g_no_h[(size_t)N_NODES * D];          // out_nodes fp16
__device__ __half g_edges_h[(size_t)N_EDGES * D];
__device__ float  g_b1p[HID];
__device__ float  g_scale[KE];
__device__ float  g_shift[KE];
__device__ float  g_psum[(size_t)STAT_BLOCKS * KE];
__device__ float  g_psq [(size_t)STAT_BLOCKS * KE];

// ---------------- helpers ------------------------------------------------
__device__ __forceinline__ float gelu_exact(float x) {
    return 0.5f * x * (1.f + erff(x * 0.70710678118654752f));
}
__device__ __forceinline__ uint32_t smem_u32(const void* p) {
    uint32_t a;
    asm("{ .reg .u64 t; cvta.to.shared.u64 t, %1; cvt.u32.u64 %0, t; }" : "=r"(a) : "l"(p));
    return a;
}
__device__ __forceinline__ void cp16s(uint32_t saddr, const void* g) {
    asm volatile("cp.async.cg.shared.global [%0], [%1], 16;" :: "r"(saddr), "l"(g));
}
#define CP_COMMIT() asm volatile("cp.async.commit_group;" ::: "memory")
#define CP_WAIT0()  asm volatile("cp.async.wait_group 0;" ::: "memory")

__device__ __forceinline__ void ldmx4(uint32_t* r, uint32_t addr) {
    asm volatile("ldmatrix.sync.aligned.m8n8.x4.shared.b16 {%0,%1,%2,%3}, [%4];"
        : "=r"(r[0]), "=r"(r[1]), "=r"(r[2]), "=r"(r[3]) : "r"(addr));
}
__device__ __forceinline__ void mma16(float* c, const uint32_t* a, const uint32_t* b) {
    asm volatile(
        "mma.sync.aligned.m16n8k16.row.col.f32.f16.f16.f32 "
        "{%0,%1,%2,%3}, {%4,%5,%6,%7}, {%8,%9}, {%0,%1,%2,%3};"
        : "+f"(c[0]), "+f"(c[1]), "+f"(c[2]), "+f"(c[3])
        : "r"(a[0]), "r"(a[1]), "r"(a[2]), "r"(a[3]), "r"(b[0]), "r"(b[1]));
}

// smem tile rows: 64 halves = 128B data + 16B pad = 144B stride
#define ROWB 144
#define ATILE (128 * ROWB)    // 18432 B (128 rows)
#define BTILE (128 * ROWB)    // 18432 B (128 n-rows)

// ---------------- small kernels ----------------------------------------------
__global__ void zero_msg_kernel() {
    int i = blockIdx.x * blockDim.x + threadIdx.x;
    if (i < N_NODES * D / 4) ((float4*)g_msg)[i] = make_float4(0.f, 0.f, 0.f, 0.f);
}

__global__ void scatter_kernel(const float* __restrict__ edges,
                               const int* __restrict__ graph) {
    long idx = (long)blockIdx.x * blockDim.x + threadIdx.x;
    if (idx >= (long)N_EDGES * D) return;
    int e = (int)(idx >> 7);
    int c = (int)(idx & 127);
    int d = __ldg(&graph[N_EDGES + e]);
    atomicAdd(&g_msg[(long)d * D + c], edges[idx]);
}

// fp32 -> fp16 stream convert (n multiple of 4)
__global__ void cvt_h_kernel(const float* __restrict__ src, __half* __restrict__ dst, long n) {
    long i = ((long)blockIdx.x * blockDim.x + threadIdx.x) * 4;
    if (i >= n) return;
    float4 v = *(const float4*)(src + i);
    __half2 h0 = __floats2half2_rn(v.x, v.y);
    __half2 h1 = __floats2half2_rn(v.z, v.w);
    *(uint2*)(dst + i) = make_uint2(*(uint32_t*)&h0, *(uint32_t*)&h1);
}

__global__ void node_stats_partial(const float* __restrict__ nodes) {
    int col = threadIdx.x;
    float s = 0.f, q = 0.f;
    for (int r = blockIdx.x; r < N_NODES; r += gridDim.x) {
        float v = (col < D) ? nodes[(long)r * D + col]
                            : g_msg[(long)r * D + (col - D)];
        s += v; q += v * v;
    }
    g_psum[(long)blockIdx.x * KN + col] = s;
    g_psq [(long)blockIdx.x * KN + col] = q;
}

__global__ void edge_stats_partial(const float* __restrict__ nodesOut,
                                   const float* __restrict__ edges,
                                   const int* __restrict__ graph) {
    int col = threadIdx.x;
    float s = 0.f, q = 0.f;
    for (int r = blockIdx.x; r < N_EDGES; r += gridDim.x) {
        float v;
        if (col < D) {
            int si = __ldg(&graph[r]);
            v = nodesOut[(long)si * D + col];
        } else if (col < 2 * D) {
            int di = __ldg(&graph[N_EDGES + r]);
            v = nodesOut[(long)di * D + (col - D)];
        } else {
            v = edges[(long)r * D + (col - 2 * D)];
        }
        s += v; q += v * v;
    }
    g_psum[(long)blockIdx.x * KE + col] = s;
    g_psq [(long)blockIdx.x * KE + col] = q;
}

__global__ void stats_finalize(int ncols, float inv_count,
                               const float* __restrict__ w,
                               const float* __restrict__ b) {
    __shared__ float rs[STAT_BLOCKS], rq[STAT_BLOCKS];
    int col = blockIdx.x;
    int t = threadIdx.x;
    rs[t] = g_psum[(long)t * ncols + col];
    rq[t] = g_psq [(long)t * ncols + col];
    __syncthreads();
    for (int off = STAT_BLOCKS / 2; off > 0; off >>= 1) {
        if (t < off) { rs[t] += rs[t + off]; rq[t] += rq[t + off]; }
        __syncthreads();
    }
    if (t == 0) {
        float mean = rs[0] * inv_count;
        float var  = fmaxf(rq[0] * inv_count - mean * mean, 0.f);
        float sc   = rsqrtf(var + EPSV) * w[col];
        g_scale[col] = sc;
        g_shift[col] = b[col] - mean * sc;
    }
}

// fold BN into W1; write TRANSPOSED [n][k] fp16
__global__ void fold_kernel(int K, const float* __restrict__ W1,
                            const float* __restrict__ b1) {
    int j = blockIdx.x * blockDim.x + threadIdx.x;
    if (j >= HID) return;
    float acc = b1[j];
    for (int k = 0; k < K; k++) {
        float wv = W1[(long)k * HID + j];
        acc += g_shift[k] * wv;
        g_W1hT[(long)j * K + k] = __float2half_rn(wv * g_scale[k]);
    }
    g_b1p[j] = acc;
}

// W2 -> transposed [n][k] fp16
__global__ void w2cvt_kernel(const float* __restrict__ W2) {
    int i = blockIdx.x * blockDim.x + threadIdx.x;
    if (i >= D * HID) return;
    int n = i >> 9, k = i & 511;
    g_W2h[i] = __float2half_rn(W2[(long)k * D + n]);
}

// ---------------- warp-tile compute: 32(m) x 64(n) x 64(k) -------------------
// A smem [m][k], B smem [n][k]; both NON-trans ldmatrix.
__device__ __forceinline__ void compute_tile64(float (&acc)[2][8][4],
                                               uint32_t sA, uint32_t sB,
                                               int wm, int wn, int lane) {
    #pragma unroll
    for (int kk = 0; kk < 64; kk += 16) {
        uint32_t a[2][4];
        #pragma unroll
        for (int mi = 0; mi < 2; mi++) {
            uint32_t addr = sA + (uint32_t)((wm + mi * 16 + (lane & 15)) * ROWB
                                            + kk * 2 + ((lane >> 4) & 1) * 16);
            ldmx4(a[mi], addr);
        }
        uint32_t b[4][4];
        #pragma unroll
        for (int nt = 0; nt < 4; nt++) {
            int nr = wn + nt * 16 + (lane & 7) + ((lane >> 4) & 1) * 8;
            int kof = kk + ((lane >> 3) & 1) * 8;
            ldmx4(b[nt], sB + (uint32_t)(nr * ROWB + kof * 2));
        }
        #pragma unroll
        for (int mi = 0; mi < 2; mi++)
            #pragma unroll
            for (int nt = 0; nt < 4; nt++) {
                mma16(acc[mi][nt * 2 + 0], a[mi], &b[nt][0]);
                mma16(acc[mi][nt * 2 + 1], a[mi], &b[nt][2]);
            }
    }
}

// ---------------- GEMM1: g_H = gelu(X @ W1 + b1) ------------------------------
// MODE 0: K=256, X[m] = [nodes_h[m], msg_h[m]]
// MODE 1: K=384, X[m] = [no_h[src[m]], no_h[dst[m]], edges_h[m]]
// CTA tile 128 x 128, 256 threads (8 warps, 4m x 2n), BK=64, all-cp.async,
// 74KB smem -> 2 CTAs/SM (bubble-hiding experiment).
#define G1_SMEM (2 * ATILE + 2 * BTILE + 512)

template <int MODE, int K>
__global__ __launch_bounds__(256, 2)
void gemm1_hmma(const int* __restrict__ graph, int M) {
    extern __shared__ __align__(16) char smem[];
    uint32_t base = smem_u32(smem);
    uint32_t sA[2] = { base,              base + ATILE };
    uint32_t sB[2] = { base + 2 * ATILE,  base + 2 * ATILE + BTILE };
    float* sBias = (float*)(smem + 2 * ATILE + 2 * BTILE);

    const int tid = threadIdx.x, lane = tid & 31, wid = tid >> 5;
    const int wm = (wid & 3) * 32, wn = (wid >> 2) * 64;
    const int rowBase = blockIdx.y * 128;
    const int nBase = blockIdx.x * 128;
    const int S = K / 64;

    if (tid < 128) sBias[tid] = g_b1p[nBase + tid];

    // A fill: 2 threads/row, 64B (32 halves) each
    const int rA = tid >> 1, h2 = tid & 1;
    const int mA = rowBase + rA;
    const int mc = (mA < M) ? mA : (M - 1);
    int vsrc = 0, vdst = 0;
    if (MODE == 1) { vsrc = graph[mc]; vdst = graph[N_EDGES + mc]; }

    float acc[2][8][4];
    #pragma unroll
    for (int i = 0; i < 2; i++)
        #pragma unroll
        for (int j = 0; j < 8; j++)
            #pragma unroll
            for (int c = 0; c < 4; c++) acc[i][j][c] = 0.f;

    auto fill = [&](int s, int buf) {
        int khalf = s * 64 + h2 * 32;
        int seg = khalf >> 7, l = khalf & 127;
        const __half* p;
        if (MODE == 0) {
            p = (seg == 0 ? g_nodes_h + (size_t)mc * D : g_msg_h + (size_t)mc * D) + l;
        } else {
            p = (seg == 0 ? g_no_h + (size_t)vsrc * D
               : seg == 1 ? g_no_h + (size_t)vdst * D
                          : g_edges_h + (size_t)mc * D) + l;
        }
        uint32_t dA = sA[buf] + (uint32_t)(rA * ROWB + h2 * 64);
        #pragma unroll
        for (int q = 0; q < 4; q++) cp16s(dA + 16 * q, p + 8 * q);
        const __half* srcB = g_W1hT + (size_t)(nBase + rA) * K + s * 64 + h2 * 32;
        uint32_t dB = sB[buf] + (uint32_t)(rA * ROWB + h2 * 64);
        #pragma unroll
        for (int q = 0; q < 4; q++) cp16s(dB + 16 * q, srcB + 8 * q);
        CP_COMMIT();
    };

    fill(0, 0);
    for (int s = 0; s < S; s++) {
        int buf = s & 1;
        CP_WAIT0();
        __syncthreads();
        if (s + 1 < S) fill(s + 1, buf ^ 1);
        compute_tile64(acc, sA[buf], sB[buf], wm, wn, lane);
    }

    // epilogue: bias + exact gelu -> fp16 g_H
    const int g = lane >> 2, tg = lane & 3;
    #pragma unroll
    for (int mi = 0; mi < 2; mi++) {
        int row0 = rowBase + wm + mi * 16 + g;
        #pragma unroll
        for (int ni = 0; ni < 8; ni++) {
            int c0 = wn + ni * 8 + tg * 2;
            int col = nBase + c0;
            float b0 = sBias[c0], b1 = sBias[c0 + 1];
            if (row0 < M) {
                __half2 hv = __floats2half2_rn(gelu_exact(acc[mi][ni][0] + b0),
                                               gelu_exact(acc[mi][ni][1] + b1));
                *(__half2*)(g_H + (size_t)row0 * HID + col) = hv;
            }
            if (row0 + 8 < M) {
                __half2 hv = __floats2half2_rn(gelu_exact(acc[mi][ni][2] + b0),
                                               gelu_exact(acc[mi][ni][3] + b1));
                *(__half2*)(g_H + (size_t)(row0 + 8) * HID + col) = hv;
            }
        }
    }
}

// ---------------- GEMM2: out = g_H @ W2 + b2 + res ----------------------------
// CTA tile 128 x 128, 256 threads, BK=64, 2 CTAs/SM.
#define G2_SMEM (2 * ATILE + 2 * BTILE + 512)

__global__ __launch_bounds__(256, 2)
void gemm2_hmma(const float* __restrict__ b2,
                const float* __restrict__ res,
                float* __restrict__ out,
                int M) {
    extern __shared__ __align__(16) char smem[];
    uint32_t base = smem_u32(smem);
    uint32_t sA[2] = { base,              base + ATILE };
    uint32_t sB[2] = { base + 2 * ATILE,  base + 2 * ATILE + BTILE };
    float* sBias = (float*)(smem + 2 * ATILE + 2 * BTILE);

    const int tid = threadIdx.x, lane = tid & 31, wid = tid >> 5;
    const int wm = (wid & 3) * 32, wn = (wid >> 2) * 64;
    const int rowBase = blockIdx.y * 128;
    const int S = HID / 64;   // 8

    if (tid < 128) sBias[tid] = b2[tid];

    const int r = tid >> 1, h2 = tid & 1;
    const int mA = rowBase + r;
    const int mc = (mA < M) ? mA : (M - 1);

    float acc[2][8][4];
    #pragma unroll
    for (int i = 0; i < 2; i++)
        #pragma unroll
        for (int j = 0; j < 8; j++)
            #pragma unroll
            for (int c = 0; c < 4; c++) acc[i][j][c] = 0.f;

    auto fill = [&](int s, int buf) {
        const __half* srcA = g_H + (size_t)mc * HID + s * 64 + h2 * 32;
        uint32_t dA = sA[buf] + (uint32_t)(r * ROWB + h2 * 64);
        #pragma unroll
        for (int q = 0; q < 4; q++) cp16s(dA + 16 * q, srcA + 8 * q);
        const __half* srcB = g_W2h + (size_t)r * HID + s * 64 + h2 * 32;
        uint32_t dB = sB[buf] + (uint32_t)(r * ROWB + h2 * 64);
        #pragma unroll
        for (int q = 0; q < 4; q++) cp16s(dB + 16 * q, srcB + 8 * q);
        CP_COMMIT();
    };

    fill(0, 0);
    for (int s = 0; s < S; s++) {
        int buf = s & 1;
        CP_WAIT0();
        __syncthreads();
        if (s + 1 < S) fill(s + 1, buf ^ 1);
        compute_tile64(acc, sA[buf], sB[buf], wm, wn, lane);
    }

    const int g = lane >> 2, tg = lane & 3;
    #pragma unroll
    for (int mi = 0; mi < 2; mi++) {
        int row0 = rowBase + wm + mi * 16 + g;
        #pragma unroll
        for (int ni = 0; ni < 8; ni++) {
            int col = wn + ni * 8 + tg * 2;
            float b0 = sBias[col], b1 = sBias[col + 1];
            if (row0 < M) {
                long o = (long)row0 * D + col;
                out[o]     = acc[mi][ni][0] + b0 + res[o];
                out[o + 1] = acc[mi][ni][1] + b1 + res[o + 1];
            }
            if (row0 + 8 < M) {
                long o = (long)(row0 + 8) * D + col;
                out[o]     = acc[mi][ni][2] + b0 + res[o];
                out[o + 1] = acc[mi][ni][3] + b1 + res[o + 1];
            }
        }
    }
}

// ---------------- launch -----------------------------------------------------
extern "C" void kernel_launch(void* const* d_in, const int* in_sizes, int n_in,
                              void* d_out, int out_size) {
    const float* nodes = (const float*)d_in[0];
    const float* edges = (const float*)d_in[1];
    const int*   graph = (const int*)  d_in[2];
    const float* nnw   = (const float*)d_in[3];
    const float* nnb   = (const float*)d_in[4];
    const float* enw   = (const float*)d_in[5];
    const float* enb   = (const float*)d_in[6];
    const float* Wn1   = (const float*)d_in[7];
    const float* bn1   = (const float*)d_in[8];
    const float* Wn2   = (const float*)d_in[9];
    const float* bn2   = (const float*)d_in[10];
    const float* We1   = (const float*)d_in[11];
    const float* be1   = (const float*)d_in[12];
    const float* We2   = (const float*)d_in[13];
    const float* be2   = (const float*)d_in[14];

    float* out_nodes = (float*)d_out;
    float* out_edges = out_nodes + (long)N_NODES * D;

    cudaFuncSetAttribute(gemm1_hmma<0, KN>, cudaFuncAttributeMaxDynamicSharedMemorySize, G1_SMEM);
    cudaFuncSetAttribute(gemm1_hmma<1, KE>, cudaFuncAttributeMaxDynamicSharedMemorySize, G1_SMEM);
    cudaFuncSetAttribute(gemm2_hmma,        cudaFuncAttributeMaxDynamicSharedMemorySize, G2_SMEM);

    __half *d_nodes_h, *d_msg_h, *d_no_h, *d_edges_h;
    float* d_msg;
    cudaGetSymbolAddress((void**)&d_nodes_h, g_nodes_h);
    cudaGetSymbolAddress((void**)&d_msg_h,   g_msg_h);
    cudaGetSymbolAddress((void**)&d_no_h,    g_no_h);
    cudaGetSymbolAddress((void**)&d_edges_h, g_edges_h);
    cudaGetSymbolAddress((void**)&d_msg,     g_msg);

    const long NN = (long)N_NODES * D, NE = (long)N_EDGES * D;

    // 1) msg = segment_sum(edges, dst); fp16 mirrors of static inputs
    zero_msg_kernel<<<(N_NODES * D / 4 + 255) / 256, 256>>>();
    scatter_kernel<<<(int)((NE + 255) / 256), 256>>>(edges, graph);
    cvt_h_kernel<<<(int)((NE / 4 + 255) / 256), 256>>>(edges, d_edges_h, NE);
    cvt_h_kernel<<<(int)((NN / 4 + 255) / 256), 256>>>(nodes, d_nodes_h, NN);
    cvt_h_kernel<<<(int)((NN / 4 + 255) / 256), 256>>>(d_msg, d_msg_h, NN);

    // 2) node batchnorm stats -> fold into W1
    node_stats_partial<<<STAT_BLOCKS, KN>>>(nodes);
    stats_finalize<<<KN, STAT_BLOCKS>>>(KN, 1.f / N_NODES, nnw, nnb);
    fold_kernel<<<(HID + 255) / 256, 256>>>(KN, Wn1, bn1);
    w2cvt_kernel<<<(D * HID + 255) / 256, 256>>>(Wn2);

    // 3) node MLP
    {
        dim3 g1(HID / 128, (N_NODES + 127) / 128);
        gemm1_hmma<0, KN><<<g1, 256, G1_SMEM>>>(nullptr, N_NODES);
        dim3 g2(1, (N_NODES + 127) / 128);
        gemm2_hmma<<<g2, 256, G2_SMEM>>>(bn2, nodes, out_nodes, N_NODES);
    }
    cvt_h_kernel<<<(int)((NN / 4 + 255) / 256), 256>>>(out_nodes, d_no_h, NN);

    // 4) edge batchnorm stats -> fold into W1
    edge_stats_partial<<<STAT_BLOCKS, KE>>>(out_nodes, edges, graph);
    stats_finalize<<<KE, STAT_BLOCKS>>>(KE, 1.f / N_EDGES, enw, enb);
    fold_kernel<<<(HID + 255) / 256, 256>>>(KE, We1, be1);
    w2cvt_kernel<<<(D * HID + 255) / 256, 256>>>(We2);

    // 5) edge MLP
    {
        dim3 g1(HID / 128, (N_EDGES + 127) / 128);
        gemm1_hmma<1, KE><<<g1, 256, G1_SMEM>>>(graph, N_EDGES);
        dim3 g2(1, (N_EDGES + 127) / 128);
        gemm2_hmma<<<g2, 256, G2_SMEM>>>(be2, edges, out_edges, N_EDGES);
    }
}

// round 12
// speedup vs baseline: 1.3763x; 1.3763x over previous
#include <cuda_runtime.h>
#include <cuda_fp16.h>
#include <math.h>
#include <stdint.h>

#define N_NODES 50000
#define N_EDGES 320000
#define D       128
#define HID     512
#define KN      256
#define KE      384
#define EPSV    1e-5f
#define NSB 256     // node-stats partial blocks
#define ESB 1024    // edge-stats partial blocks

// ---------------- device scratch (allocation-free: static globals) ----------
__device__ float  g_msg[(size_t)N_NODES * D];           // fp32 scatter target
__device__ __half g_H[(size_t)N_EDGES * HID];           // hidden acts fp16
__device__ __half g_W1hT[(size_t)HID * KE];             // folded W1 [n][k] fp16
__device__ __half g_W2h[(size_t)D * HID];               // W2 [n][k] fp16
__device__ __half g_nodes_h[(size_t)N_NODES * D];       // fp16 mirrors
__device__ __half g_msg_h[(size_t)N_NODES * D];
__device__ __half g_no_h[(size_t)N_NODES * D];          // out_nodes fp16
__device__ __half g_edges_h[(size_t)N_EDGES * D];
__device__ int    g_deg_src[N_NODES];
__device__ int    g_deg_dst[N_NODES];
__device__ float  g_b1p[HID];
__device__ float  g_scale[KE];
__device__ float  g_shift[KE];
__device__ float  g_psum [(size_t)NSB * KN];            // node stats partials
__device__ float  g_psq  [(size_t)NSB * KN];
__device__ float  g_epsum[(size_t)ESB * KE];            // edge stats partials (SEPARATE!)
__device__ float  g_epsq [(size_t)ESB * KE];

// ---------------- helpers ------------------------------------------------
__device__ __forceinline__ float gelu_exact(float x) {
    return 0.5f * x * (1.f + erff(x * 0.70710678118654752f));
}
__device__ __forceinline__ uint32_t smem_u32(const void* p) {
    uint32_t a;
    asm("{ .reg .u64 t; cvta.to.shared.u64 t, %1; cvt.u32.u64 %0, t; }" : "=r"(a) : "l"(p));
    return a;
}
__device__ __forceinline__ void cp16s(uint32_t saddr, const void* g) {
    asm volatile("cp.async.cg.shared.global [%0], [%1], 16;" :: "r"(saddr), "l"(g));
}
#define CP_COMMIT() asm volatile("cp.async.commit_group;" ::: "memory")
#define CP_WAIT0()  asm volatile("cp.async.wait_group 0;" ::: "memory")

__device__ __forceinline__ void ldmx4(uint32_t* r, uint32_t addr) {
    asm volatile("ldmatrix.sync.aligned.m8n8.x4.shared.b16 {%0,%1,%2,%3}, [%4];"
        : "=r"(r[0]), "=r"(r[1]), "=r"(r[2]), "=r"(r[3]) : "r"(addr));
}
__device__ __forceinline__ void mma16(float* c, const uint32_t* a, const uint32_t* b) {
    asm volatile(
        "mma.sync.aligned.m16n8k16.row.col.f32.f16.f16.f32 "
        "{%0,%1,%2,%3}, {%4,%5,%6,%7}, {%8,%9}, {%0,%1,%2,%3};"
        : "+f"(c[0]), "+f"(c[1]), "+f"(c[2]), "+f"(c[3])
        : "r"(a[0]), "r"(a[1]), "r"(a[2]), "r"(a[3]), "r"(b[0]), "r"(b[1]));
}

// smem tile rows: 64 halves = 128B data + 16B pad = 144B stride
#define ROWB 144
#define ATILE (128 * ROWB)
#define BTILE (128 * ROWB)

// ---------------- small kernels ----------------------------------------------
__global__ void zero_msg_kernel() {
    int i = blockIdx.x * blockDim.x + threadIdx.x;
    if (i < N_NODES * D / 4) ((float4*)g_msg)[i] = make_float4(0.f, 0.f, 0.f, 0.f);
}

__global__ void deg_count_kernel(const int* __restrict__ graph) {
    int e = blockIdx.x * blockDim.x + threadIdx.x;
    if (e >= N_EDGES) return;
    atomicAdd(&g_deg_src[__ldg(&graph[e])], 1);
    atomicAdd(&g_deg_dst[__ldg(&graph[N_EDGES + e])], 1);
}

// ONE pass over edges: scatter-add into msg + fp16 mirror + edge-stats cols 256..383
__global__ void edge_fused_kernel(const float* __restrict__ edges,
                                  const int* __restrict__ graph) {
    int t = threadIdx.x;   // 0..127
    float s = 0.f, q = 0.f;
    for (int e = blockIdx.x; e < N_EDGES; e += gridDim.x) {
        int dd = __ldg(&graph[N_EDGES + e]);
        float v = edges[(size_t)e * D + t];
        atomicAdd(&g_msg[(size_t)dd * D + t], v);
        g_edges_h[(size_t)e * D + t] = __float2half_rn(v);
        s += v; q += v * v;
    }
    g_epsum[(size_t)blockIdx.x * KE + 2 * D + t] = s;
    g_epsq [(size_t)blockIdx.x * KE + 2 * D + t] = q;
}

// node stats over [nodes | msg] + write fp16 mirrors
__global__ void node_stats_partial(const float* __restrict__ nodes) {
    int col = threadIdx.x;   // 0..255
    float s = 0.f, q = 0.f;
    for (int r = blockIdx.x; r < N_NODES; r += gridDim.x) {
        float v;
        if (col < D) {
            v = nodes[(size_t)r * D + col];
            g_nodes_h[(size_t)r * D + col] = __float2half_rn(v);
        } else {
            v = g_msg[(size_t)r * D + (col - D)];
            g_msg_h[(size_t)r * D + (col - D)] = __float2half_rn(v);
        }
        s += v; q += v * v;
    }
    g_psum[(size_t)blockIdx.x * KN + col] = s;
    g_psq [(size_t)blockIdx.x * KN + col] = q;
}

// edge-stats cols 0..255 via degree weighting over out_nodes
__global__ void edge_stats_deg(const float* __restrict__ nodesOut) {
    int t = threadIdx.x;        // 0..255
    int c = t & (D - 1);
    float s = 0.f, q = 0.f;
    for (int v = blockIdx.x; v < N_NODES; v += gridDim.x) {
        float x = nodesOut[(size_t)v * D + c];
        float w = (float)((t < D) ? g_deg_src[v] : g_deg_dst[v]);
        s += w * x;
        q += w * x * x;
    }
    g_epsum[(size_t)blockIdx.x * KE + t] = s;
    g_epsq [(size_t)blockIdx.x * KE + t] = q;
}

// finalize: one block per column; blockDim = number of partial blocks (pow2)
// EDGE=0 reads g_psum/g_psq (stride KN); EDGE=1 reads g_epsum/g_epsq (stride KE)
template <int EDGE>
__global__ void stats_finalize(int ncols, float inv_count,
                               const float* __restrict__ w,
                               const float* __restrict__ b) {
    __shared__ float rs[ESB], rq[ESB];
    int col = blockIdx.x;
    int t = threadIdx.x;
    if (EDGE) {
        rs[t] = g_epsum[(size_t)t * ncols + col];
        rq[t] = g_epsq [(size_t)t * ncols + col];
    } else {
        rs[t] = g_psum[(size_t)t * ncols + col];
        rq[t] = g_psq [(size_t)t * ncols + col];
    }
    __syncthreads();
    for (int off = blockDim.x / 2; off > 0; off >>= 1) {
        if (t < off) { rs[t] += rs[t + off]; rq[t] += rq[t + off]; }
        __syncthreads();
    }
    if (t == 0) {
        float mean = rs[0] * inv_count;
        float var  = fmaxf(rq[0] * inv_count - mean * mean, 0.f);
        float sc   = rsqrtf(var + EPSV) * w[col];
        g_scale[col] = sc;
        g_shift[col] = b[col] - mean * sc;
    }
}

// fold BN into W1; write TRANSPOSED [n][k] fp16
__global__ void fold_kernel(int K, const float* __restrict__ W1,
                            const float* __restrict__ b1) {
    int j = blockIdx.x * blockDim.x + threadIdx.x;
    if (j >= HID) return;
    float acc = b1[j];
    for (int k = 0; k < K; k++) {
        float wv = W1[(size_t)k * HID + j];
        acc += g_shift[k] * wv;
        g_W1hT[(size_t)j * K + k] = __float2half_rn(wv * g_scale[k]);
    }
    g_b1p[j] = acc;
}

// W2 -> transposed [n][k] fp16
__global__ void w2cvt_kernel(const float* __restrict__ W2) {
    int i = blockIdx.x * blockDim.x + threadIdx.x;
    if (i >= D * HID) return;
    int n = i >> 9, k = i & 511;
    g_W2h[i] = __float2half_rn(W2[(size_t)k * D + n]);
}

// ---------------- warp-tile compute: 32(m) x 64(n) x 64(k) -------------------
__device__ __forceinline__ void compute_tile64(float (&acc)[2][8][4],
                                               uint32_t sA, uint32_t sB,
                                               int wm, int wn, int lane) {
    #pragma unroll
    for (int kk = 0; kk < 64; kk += 16) {
        uint32_t a[2][4];
        #pragma unroll
        for (int mi = 0; mi < 2; mi++) {
            uint32_t addr = sA + (uint32_t)((wm + mi * 16 + (lane & 15)) * ROWB
                                            + kk * 2 + ((lane >> 4) & 1) * 16);
            ldmx4(a[mi], addr);
        }
        uint32_t b[4][4];
        #pragma unroll
        for (int nt = 0; nt < 4; nt++) {
            int nr = wn + nt * 16 + (lane & 7) + ((lane >> 4) & 1) * 8;
            int kof = kk + ((lane >> 3) & 1) * 8;
            ldmx4(b[nt], sB + (uint32_t)(nr * ROWB + kof * 2));
        }
        #pragma unroll
        for (int mi = 0; mi < 2; mi++)
            #pragma unroll
            for (int nt = 0; nt < 4; nt++) {
                mma16(acc[mi][nt * 2 + 0], a[mi], &b[nt][0]);
                mma16(acc[mi][nt * 2 + 1], a[mi], &b[nt][2]);
            }
    }
}

// ---------------- GEMM1: g_H = gelu(X @ W1 + b1) ------------------------------
#define G1_SMEM (2 * ATILE + 2 * BTILE + 512)

template <int MODE, int K>
__global__ __launch_bounds__(256, 2)
void gemm1_hmma(const int* __restrict__ graph, int M) {
    extern __shared__ __align__(16) char smem[];
    uint32_t base = smem_u32(smem);
    uint32_t sA[2] = { base,              base + ATILE };
    uint32_t sB[2] = { base + 2 * ATILE,  base + 2 * ATILE + BTILE };
    float* sBias = (float*)(smem + 2 * ATILE + 2 * BTILE);

    const int tid = threadIdx.x, lane = tid & 31, wid = tid >> 5;
    const int wm = (wid & 3) * 32, wn = (wid >> 2) * 64;
    const int rowBase = blockIdx.y * 128;
    const int nBase = blockIdx.x * 128;
    const int S = K / 64;

    if (tid < 128) sBias[tid] = g_b1p[nBase + tid];

    const int rA = tid >> 1, h2 = tid & 1;
    const int mA = rowBase + rA;
    const int mc = (mA < M) ? mA : (M - 1);
    int vsrc = 0, vdst = 0;
    if (MODE == 1) { vsrc = graph[mc]; vdst = graph[N_EDGES + mc]; }

    float acc[2][8][4];
    #pragma unroll
    for (int i = 0; i < 2; i++)
        #pragma unroll
        for (int j = 0; j < 8; j++)
            #pragma unroll
            for (int c = 0; c < 4; c++) acc[i][j][c] = 0.f;

    auto fill = [&](int s, int buf) {
        int khalf = s * 64 + h2 * 32;
        int seg = khalf >> 7, l = khalf & 127;
        const __half* p;
        if (MODE == 0) {
            p = (seg == 0 ? g_nodes_h + (size_t)mc * D : g_msg_h + (size_t)mc * D) + l;
        } else {
            p = (seg == 0 ? g_no_h + (size_t)vsrc * D
               : seg == 1 ? g_no_h + (size_t)vdst * D
                          : g_edges_h + (size_t)mc * D) + l;
        }
        uint32_t dA = sA[buf] + (uint32_t)(rA * ROWB + h2 * 64);
        #pragma unroll
        for (int q = 0; q < 4; q++) cp16s(dA + 16 * q, p + 8 * q);
        const __half* srcB = g_W1hT + (size_t)(nBase + rA) * K + s * 64 + h2 * 32;
        uint32_t dB = sB[buf] + (uint32_t)(rA * ROWB + h2 * 64);
        #pragma unroll
        for (int q = 0; q < 4; q++) cp16s(dB + 16 * q, srcB + 8 * q);
        CP_COMMIT();
    };

    fill(0, 0);
    for (int s = 0; s < S; s++) {
        int buf = s & 1;
        CP_WAIT0();
        __syncthreads();
        if (s + 1 < S) fill(s + 1, buf ^ 1);
        compute_tile64(acc, sA[buf], sB[buf], wm, wn, lane);
    }

    const int g = lane >> 2, tg = lane & 3;
    #pragma unroll
    for (int mi = 0; mi < 2; mi++) {
        int row0 = rowBase + wm + mi * 16 + g;
        #pragma unroll
        for (int ni = 0; ni < 8; ni++) {
            int c0 = wn + ni * 8 + tg * 2;
            int col = nBase + c0;
            float b0 = sBias[c0], b1 = sBias[c0 + 1];
            if (row0 < M) {
                __half2 hv = __floats2half2_rn(gelu_exact(acc[mi][ni][0] + b0),
                                               gelu_exact(acc[mi][ni][1] + b1));
                *(__half2*)(g_H + (size_t)row0 * HID + col) = hv;
            }
            if (row0 + 8 < M) {
                __half2 hv = __floats2half2_rn(gelu_exact(acc[mi][ni][2] + b0),
                                               gelu_exact(acc[mi][ni][3] + b1));
                *(__half2*)(g_H + (size_t)(row0 + 8) * HID + col) = hv;
            }
        }
    }
}

// ---------------- GEMM2: out = g_H @ W2 + b2 + res (+ optional fp16 mirror) ---
#define G2_SMEM (2 * ATILE + 2 * BTILE + 512)

__global__ __launch_bounds__(256, 2)
void gemm2_hmma(const float* __restrict__ b2,
                const float* __restrict__ res,
                float* __restrict__ out,
                __half* __restrict__ out_h,
                int M) {
    extern __shared__ __align__(16) char smem[];
    uint32_t base = smem_u32(smem);
    uint32_t sA[2] = { base,              base + ATILE };
    uint32_t sB[2] = { base + 2 * ATILE,  base + 2 * ATILE + BTILE };
    float* sBias = (float*)(smem + 2 * ATILE + 2 * BTILE);

    const int tid = threadIdx.x, lane = tid & 31, wid = tid >> 5;
    const int wm = (wid & 3) * 32, wn = (wid >> 2) * 64;
    const int rowBase = blockIdx.y * 128;
    const int S = HID / 64;

    if (tid < 128) sBias[tid] = b2[tid];

    const int r = tid >> 1, h2 = tid & 1;
    const int mA = rowBase + r;
    const int mc = (mA < M) ? mA : (M - 1);

    float acc[2][8][4];
    #pragma unroll
    for (int i = 0; i < 2; i++)
        #pragma unroll
        for (int j = 0; j < 8; j++)
            #pragma unroll
            for (int c = 0; c < 4; c++) acc[i][j][c] = 0.f;

    auto fill = [&](int s, int buf) {
        const __half* srcA = g_H + (size_t)mc * HID + s * 64 + h2 * 32;
        uint32_t dA = sA[buf] + (uint32_t)(r * ROWB + h2 * 64);
        #pragma unroll
        for (int q = 0; q < 4; q++) cp16s(dA + 16 * q, srcA + 8 * q);
        const __half* srcB = g_W2h + (size_t)r * HID + s * 64 + h2 * 32;
        uint32_t dB = sB[buf] + (uint32_t)(r * ROWB + h2 * 64);
        #pragma unroll
        for (int q = 0; q < 4; q++) cp16s(dB + 16 * q, srcB + 8 * q);
        CP_COMMIT();
    };

    fill(0, 0);
    for (int s = 0; s < S; s++) {
        int buf = s & 1;
        CP_WAIT0();
        __syncthreads();
        if (s + 1 < S) fill(s + 1, buf ^ 1);
        compute_tile64(acc, sA[buf], sB[buf], wm, wn, lane);
    }

    const int g = lane >> 2, tg = lane & 3;
    #pragma unroll
    for (int mi = 0; mi < 2; mi++) {
        int row0 = rowBase + wm + mi * 16 + g;
        #pragma unroll
        for (int ni = 0; ni < 8; ni++) {
            int col = wn + ni * 8 + tg * 2;
            float b0 = sBias[col], b1 = sBias[col + 1];
            if (row0 < M) {
                size_t o = (size_t)row0 * D + col;
                float v0 = acc[mi][ni][0] + b0 + res[o];
                float v1 = acc[mi][ni][1] + b1 + res[o + 1];
                out[o] = v0; out[o + 1] = v1;
                if (out_h) *(__half2*)(out_h + o) = __floats2half2_rn(v0, v1);
            }
            if (row0 + 8 < M) {
                size_t o = (size_t)(row0 + 8) * D + col;
                float v0 = acc[mi][ni][2] + b0 + res[o];
                float v1 = acc[mi][ni][3] + b1 + res[o + 1];
                out[o] = v0; out[o + 1] = v1;
                if (out_h) *(__half2*)(out_h + o) = __floats2half2_rn(v0, v1);
            }
        }
    }
}

// ---------------- launch -----------------------------------------------------
extern "C" void kernel_launch(void* const* d_in, const int* in_sizes, int n_in,
                              void* d_out, int out_size) {
    const float* nodes = (const float*)d_in[0];
    const float* edges = (const float*)d_in[1];
    const int*   graph = (const int*)  d_in[2];
    const float* nnw   = (const float*)d_in[3];
    const float* nnb   = (const float*)d_in[4];
    const float* enw   = (const float*)d_in[5];
    const float* enb   = (const float*)d_in[6];
    const float* Wn1   = (const float*)d_in[7];
    const float* bn1   = (const float*)d_in[8];
    const float* Wn2   = (const float*)d_in[9];
    const float* bn2   = (const float*)d_in[10];
    const float* We1   = (const float*)d_in[11];
    const float* be1   = (const float*)d_in[12];
    const float* We2   = (const float*)d_in[13];
    const float* be2   = (const float*)d_in[14];

    float* out_nodes = (float*)d_out;
    float* out_edges = out_nodes + (size_t)N_NODES * D;

    cudaFuncSetAttribute(gemm1_hmma<0, KN>, cudaFuncAttributeMaxDynamicSharedMemorySize, G1_SMEM);
    cudaFuncSetAttribute(gemm1_hmma<1, KE>, cudaFuncAttributeMaxDynamicSharedMemorySize, G1_SMEM);
    cudaFuncSetAttribute(gemm2_hmma,        cudaFuncAttributeMaxDynamicSharedMemorySize, G2_SMEM);

    __half* d_no_h;
    int *d_deg_src, *d_deg_dst;
    cudaGetSymbolAddress((void**)&d_no_h,    g_no_h);
    cudaGetSymbolAddress((void**)&d_deg_src, g_deg_src);
    cudaGetSymbolAddress((void**)&d_deg_dst, g_deg_dst);

    // 1) zero msg + degree counts; fused edge pass (scatter + fp16 mirror + stats)
    zero_msg_kernel<<<(N_NODES * D / 4 + 255) / 256, 256>>>();
    cudaMemsetAsync(d_deg_src, 0, N_NODES * sizeof(int));
    cudaMemsetAsync(d_deg_dst, 0, N_NODES * sizeof(int));
    deg_count_kernel<<<(N_EDGES + 255) / 256, 256>>>(graph);
    edge_fused_kernel<<<ESB, 128>>>(edges, graph);

    // 2) node batchnorm stats (also emits nodes_h / msg_h) -> fold into W1
    node_stats_partial<<<NSB, KN>>>(nodes);
    stats_finalize<0><<<KN, NSB>>>(KN, 1.f / N_NODES, nnw, nnb);
    fold_kernel<<<(HID + 255) / 256, 256>>>(KN, Wn1, bn1);
    w2cvt_kernel<<<(D * HID + 255) / 256, 256>>>(Wn2);

    // 3) node MLP (gemm2 also emits no_h mirror)
    {
        dim3 g1(HID / 128, (N_NODES + 127) / 128);
        gemm1_hmma<0, KN><<<g1, 256, G1_SMEM>>>(nullptr, N_NODES);
        dim3 g2(1, (N_NODES + 127) / 128);
        gemm2_hmma<<<g2, 256, G2_SMEM>>>(bn2, nodes, out_nodes, d_no_h, N_NODES);
    }

    // 4) edge batchnorm stats: cols 0..255 degree-weighted, cols 256..383 from fused pass
    edge_stats_deg<<<ESB, 256>>>(out_nodes);
    stats_finalize<1><<<KE, ESB>>>(KE, 1.f / N_EDGES, enw, enb);
    fold_kernel<<<(HID + 255) / 256, 256>>>(KE, We1, be1);
    w2cvt_kernel<<<(D * HID + 255) / 256, 256>>>(We2);

    // 5) edge MLP
    {
        dim3 g1(HID / 128, (N_EDGES + 127) / 128);
        gemm1_hmma<1, KE><<<g1, 256, G1_SMEM>>>(graph, N_EDGES);
        dim3 g2(1, (N_EDGES + 127) / 128);
        gemm2_hmma<<<g2, 256, G2_SMEM>>>(be2, edges, out_edges, nullptr, N_EDGES);
    }
}

// round 13
// speedup vs baseline: 1.5030x; 1.0921x over previous
#include <cuda_runtime.h>
#include <cuda_fp16.h>
#include <math.h>
#include <stdint.h>

#define N_NODES 50000
#define N_EDGES 320000
#define D       128
#define HID     512
#define KN      256
#define KE      384
#define EPSV    1e-5f
#define NSB 1024    // node-stats partial blocks
#define ESB 2048    // edge-stats partial blocks
#define FINT 1024   // finalize threads

// ---------------- device scratch (allocation-free: static globals) ----------
__device__ float  g_msg[(size_t)N_NODES * D];           // fp32 scatter target
__device__ __half g_H[(size_t)N_EDGES * HID];           // hidden acts fp16
__device__ __half g_W1hT[(size_t)HID * KE];             // folded W1 [n][k] fp16
__device__ __half g_W2h[(size_t)D * HID];               // W2 [n][k] fp16
__device__ __half g_nodes_h[(size_t)N_NODES * D];       // fp16 mirrors
__device__ __half g_msg_h[(size_t)N_NODES * D];
__device__ __half g_no_h[(size_t)N_NODES * D];          // out_nodes fp16
__device__ __half g_edges_h[(size_t)N_EDGES * D];
__device__ int    g_deg_src[N_NODES];
__device__ int    g_deg_dst[N_NODES];
__device__ float  g_b1p[HID];
__device__ float  g_scale[KE];
__device__ float  g_shift[KE];
__device__ float  g_psum [(size_t)NSB * KN];            // node stats partials
__device__ float  g_psq  [(size_t)NSB * KN];
__device__ float  g_epsum[(size_t)ESB * KE];            // edge stats partials
__device__ float  g_epsq [(size_t)ESB * KE];

// ---------------- helpers ------------------------------------------------
__device__ __forceinline__ float gelu_exact(float x) {
    return 0.5f * x * (1.f + erff(x * 0.70710678118654752f));
}
__device__ __forceinline__ uint32_t smem_u32(const void* p) {
    uint32_t a;
    asm("{ .reg .u64 t; cvta.to.shared.u64 t, %1; cvt.u32.u64 %0, t; }" : "=r"(a) : "l"(p));
    return a;
}
__device__ __forceinline__ void cp16s(uint32_t saddr, const void* g) {
    asm volatile("cp.async.cg.shared.global [%0], [%1], 16;" :: "r"(saddr), "l"(g));
}
#define CP_COMMIT() asm volatile("cp.async.commit_group;" ::: "memory")
#define CP_WAIT0()  asm volatile("cp.async.wait_group 0;" ::: "memory")

__device__ __forceinline__ void ldmx4(uint32_t* r, uint32_t addr) {
    asm volatile("ldmatrix.sync.aligned.m8n8.x4.shared.b16 {%0,%1,%2,%3}, [%4];"
        : "=r"(r[0]), "=r"(r[1]), "=r"(r[2]), "=r"(r[3]) : "r"(addr));
}
__device__ __forceinline__ void mma16(float* c, const uint32_t* a, const uint32_t* b) {
    asm volatile(
        "mma.sync.aligned.m16n8k16.row.col.f32.f16.f16.f32 "
        "{%0,%1,%2,%3}, {%4,%5,%6,%7}, {%8,%9}, {%0,%1,%2,%3};"
        : "+f"(c[0]), "+f"(c[1]), "+f"(c[2]), "+f"(c[3])
        : "r"(a[0]), "r"(a[1]), "r"(a[2]), "r"(a[3]), "r"(b[0]), "r"(b[1]));
}

// smem tile rows: 64 halves = 128B data + 16B pad = 144B stride
#define ROWB 144
#define ATILE (128 * ROWB)
#define BTILE (128 * ROWB)

// ---------------- small kernels ----------------------------------------------
__global__ void zero_msg_kernel() {
    int i = blockIdx.x * blockDim.x + threadIdx.x;
    if (i < N_NODES * D / 4) ((float4*)g_msg)[i] = make_float4(0.f, 0.f, 0.f, 0.f);
}

__global__ void deg_count_kernel(const int* __restrict__ graph) {
    int e = blockIdx.x * blockDim.x + threadIdx.x;
    if (e >= N_EDGES) return;
    atomicAdd(&g_deg_src[__ldg(&graph[e])], 1);
    atomicAdd(&g_deg_dst[__ldg(&graph[N_EDGES + e])], 1);
}

// ONE pass over edges: scatter-add into msg + fp16 mirror + edge-stats cols 256..383
__global__ void edge_fused_kernel(const float* __restrict__ edges,
                                  const int* __restrict__ graph) {
    int t = threadIdx.x;   // 0..127
    float s = 0.f, q = 0.f;
    for (int e = blockIdx.x; e < N_EDGES; e += gridDim.x) {
        int dd = __ldg(&graph[N_EDGES + e]);
        float v = edges[(size_t)e * D + t];
        atomicAdd(&g_msg[(size_t)dd * D + t], v);
        g_edges_h[(size_t)e * D + t] = __float2half_rn(v);
        s += v; q += v * v;
    }
    g_epsum[(size_t)blockIdx.x * KE + 2 * D + t] = s;
    g_epsq [(size_t)blockIdx.x * KE + 2 * D + t] = q;
}

// node stats over [nodes | msg] + write fp16 mirrors
__global__ void node_stats_partial(const float* __restrict__ nodes) {
    int col = threadIdx.x;   // 0..255
    float s = 0.f, q = 0.f;
    for (int r = blockIdx.x; r < N_NODES; r += gridDim.x) {
        float v;
        if (col < D) {
            v = nodes[(size_t)r * D + col];
            g_nodes_h[(size_t)r * D + col] = __float2half_rn(v);
        } else {
            v = g_msg[(size_t)r * D + (col - D)];
            g_msg_h[(size_t)r * D + (col - D)] = __float2half_rn(v);
        }
        s += v; q += v * v;
    }
    g_psum[(size_t)blockIdx.x * KN + col] = s;
    g_psq [(size_t)blockIdx.x * KN + col] = q;
}

// edge-stats cols 0..255 via degree weighting over out_nodes
__global__ void edge_stats_deg(const float* __restrict__ nodesOut) {
    int t = threadIdx.x;        // 0..255
    int c = t & (D - 1);
    float s = 0.f, q = 0.f;
    for (int v = blockIdx.x; v < N_NODES; v += gridDim.x) {
        float x = nodesOut[(size_t)v * D + c];
        float w = (float)((t < D) ? g_deg_src[v] : g_deg_dst[v]);
        s += w * x;
        q += w * x * x;
    }
    g_epsum[(size_t)blockIdx.x * KE + t] = s;
    g_epsq [(size_t)blockIdx.x * KE + t] = q;
}

// finalize: one block per column; FINT threads; each thread strided-accumulates
// nparts/FINT partials, then tree-reduce.
template <int EDGE>
__global__ void stats_finalize(int ncols, int nparts, float inv_count,
                               const float* __restrict__ w,
                               const float* __restrict__ b) {
    __shared__ float rs[FINT], rq[FINT];
    int col = blockIdx.x;
    int t = threadIdx.x;
    float s = 0.f, q = 0.f;
    for (int p = t; p < nparts; p += FINT) {
        if (EDGE) {
            s += g_epsum[(size_t)p * ncols + col];
            q += g_epsq [(size_t)p * ncols + col];
        } else {
            s += g_psum[(size_t)p * ncols + col];
            q += g_psq [(size_t)p * ncols + col];
        }
    }
    rs[t] = s; rq[t] = q;
    __syncthreads();
    for (int off = FINT / 2; off > 0; off >>= 1) {
        if (t < off) { rs[t] += rs[t + off]; rq[t] += rq[t + off]; }
        __syncthreads();
    }
    if (t == 0) {
        float mean = rs[0] * inv_count;
        float var  = fmaxf(rq[0] * inv_count - mean * mean, 0.f);
        float sc   = rsqrtf(var + EPSV) * w[col];
        g_scale[col] = sc;
        g_shift[col] = b[col] - mean * sc;
    }
}

// fold BN into W1; write TRANSPOSED [n][k] fp16
__global__ void fold_kernel(int K, const float* __restrict__ W1,
                            const float* __restrict__ b1) {
    int j = blockIdx.x * blockDim.x + threadIdx.x;
    if (j >= HID) return;
    float acc = b1[j];
    for (int k = 0; k < K; k++) {
        float wv = W1[(size_t)k * HID + j];
        acc += g_shift[k] * wv;
        g_W1hT[(size_t)j * K + k] = __float2half_rn(wv * g_scale[k]);
    }
    g_b1p[j] = acc;
}

// W2 -> transposed [n][k] fp16
__global__ void w2cvt_kernel(const float* __restrict__ W2) {
    int i = blockIdx.x * blockDim.x + threadIdx.x;
    if (i >= D * HID) return;
    int n = i >> 9, k = i & 511;
    g_W2h[i] = __float2half_rn(W2[(size_t)k * D + n]);
}

// ---------------- warp-tile compute: 32(m) x 64(n) x 64(k) -------------------
__device__ __forceinline__ void compute_tile64(float (&acc)[2][8][4],
                                               uint32_t sA, uint32_t sB,
                                               int wm, int wn, int lane) {
    #pragma unroll
    for (int kk = 0; kk < 64; kk += 16) {
        uint32_t a[2][4];
        #pragma unroll
        for (int mi = 0; mi < 2; mi++) {
            uint32_t addr = sA + (uint32_t)((wm + mi * 16 + (lane & 15)) * ROWB
                                            + kk * 2 + ((lane >> 4) & 1) * 16);
            ldmx4(a[mi], addr);
        }
        uint32_t b[4][4];
        #pragma unroll
        for (int nt = 0; nt < 4; nt++) {
            int nr = wn + nt * 16 + (lane & 7) + ((lane >> 4) & 1) * 8;
            int kof = kk + ((lane >> 3) & 1) * 8;
            ldmx4(b[nt], sB + (uint32_t)(nr * ROWB + kof * 2));
        }
        #pragma unroll
        for (int mi = 0; mi < 2; mi++)
            #pragma unroll
            for (int nt = 0; nt < 4; nt++) {
                mma16(acc[mi][nt * 2 + 0], a[mi], &b[nt][0]);
                mma16(acc[mi][nt * 2 + 1], a[mi], &b[nt][2]);
            }
    }
}

// ---------------- GEMM1: g_H = gelu(X @ W1 + b1) ------------------------------
#define G1_SMEM (2 * ATILE + 2 * BTILE + 512)

template <int MODE, int K>
__global__ __launch_bounds__(256, 2)
void gemm1_hmma(const int* __restrict__ graph, int M) {
    extern __shared__ __align__(16) char smem[];
    uint32_t base = smem_u32(smem);
    uint32_t sA[2] = { base,              base + ATILE };
    uint32_t sB[2] = { base + 2 * ATILE,  base + 2 * ATILE + BTILE };
    float* sBias = (float*)(smem + 2 * ATILE + 2 * BTILE);

    const int tid = threadIdx.x, lane = tid & 31, wid = tid >> 5;
    const int wm = (wid & 3) * 32, wn = (wid >> 2) * 64;
    const int rowBase = blockIdx.y * 128;
    const int nBase = blockIdx.x * 128;
    const int S = K / 64;

    if (tid < 128) sBias[tid] = g_b1p[nBase + tid];

    const int rA = tid >> 1, h2 = tid & 1;
    const int mA = rowBase + rA;
    const int mc = (mA < M) ? mA : (M - 1);
    int vsrc = 0, vdst = 0;
    if (MODE == 1) { vsrc = graph[mc]; vdst = graph[N_EDGES + mc]; }

    float acc[2][8][4];
    #pragma unroll
    for (int i = 0; i < 2; i++)
        #pragma unroll
        for (int j = 0; j < 8; j++)
            #pragma unroll
            for (int c = 0; c < 4; c++) acc[i][j][c] = 0.f;

    auto fill = [&](int s, int buf) {
        int khalf = s * 64 + h2 * 32;
        int seg = khalf >> 7, l = khalf & 127;
        const __half* p;
        if (MODE == 0) {
            p = (seg == 0 ? g_nodes_h + (size_t)mc * D : g_msg_h + (size_t)mc * D) + l;
        } else {
            p = (seg == 0 ? g_no_h + (size_t)vsrc * D
               : seg == 1 ? g_no_h + (size_t)vdst * D
                          : g_edges_h + (size_t)mc * D) + l;
        }
        uint32_t dA = sA[buf] + (uint32_t)(rA * ROWB + h2 * 64);
        #pragma unroll
        for (int q = 0; q < 4; q++) cp16s(dA + 16 * q, p + 8 * q);
        const __half* srcB = g_W1hT + (size_t)(nBase + rA) * K + s * 64 + h2 * 32;
        uint32_t dB = sB[buf] + (uint32_t)(rA * ROWB + h2 * 64);
        #pragma unroll
        for (int q = 0; q < 4; q++) cp16s(dB + 16 * q, srcB + 8 * q);
        CP_COMMIT();
    };

    fill(0, 0);
    for (int s = 0; s < S; s++) {
        int buf = s & 1;
        CP_WAIT0();
        __syncthreads();
        if (s + 1 < S) fill(s + 1, buf ^ 1);
        compute_tile64(acc, sA[buf], sB[buf], wm, wn, lane);
    }

    const int g = lane >> 2, tg = lane & 3;
    #pragma unroll
    for (int mi = 0; mi < 2; mi++) {
        int row0 = rowBase + wm + mi * 16 + g;
        #pragma unroll
        for (int ni = 0; ni < 8; ni++) {
            int c0 = wn + ni * 8 + tg * 2;
            int col = nBase + c0;
            float b0 = sBias[c0], b1 = sBias[c0 + 1];
            if (row0 < M) {
                __half2 hv = __floats2half2_rn(gelu_exact(acc[mi][ni][0] + b0),
                                               gelu_exact(acc[mi][ni][1] + b1));
                *(__half2*)(g_H + (size_t)row0 * HID + col) = hv;
            }
            if (row0 + 8 < M) {
                __half2 hv = __floats2half2_rn(gelu_exact(acc[mi][ni][2] + b0),
                                               gelu_exact(acc[mi][ni][3] + b1));
                *(__half2*)(g_H + (size_t)(row0 + 8) * HID + col) = hv;
            }
        }
    }
}

// ---------------- GEMM2: out = g_H @ W2 + b2 + res (+ optional fp16 mirror) ---
#define G2_SMEM (2 * ATILE + 2 * BTILE + 512)

__global__ __launch_bounds__(256, 2)
void gemm2_hmma(const float* __restrict__ b2,
                const float* __restrict__ res,
                float* __restrict__ out,
                __half* __restrict__ out_h,
                int M) {
    extern __shared__ __align__(16) char smem[];
    uint32_t base = smem_u32(smem);
    uint32_t sA[2] = { base,              base + ATILE };
    uint32_t sB[2] = { base + 2 * ATILE,  base + 2 * ATILE + BTILE };
    float* sBias = (float*)(smem + 2 * ATILE + 2 * BTILE);

    const int tid = threadIdx.x, lane = tid & 31, wid = tid >> 5;
    const int wm = (wid & 3) * 32, wn = (wid >> 2) * 64;
    const int rowBase = blockIdx.y * 128;
    const int S = HID / 64;

    if (tid < 128) sBias[tid] = b2[tid];

    const int r = tid >> 1, h2 = tid & 1;
    const int mA = rowBase + r;
    const int mc = (mA < M) ? mA : (M - 1);

    float acc[2][8][4];
    #pragma unroll
    for (int i = 0; i < 2; i++)
        #pragma unroll
        for (int j = 0; j < 8; j++)
            #pragma unroll
            for (int c = 0; c < 4; c++) acc[i][j][c] = 0.f;

    auto fill = [&](int s, int buf) {
        const __half* srcA = g_H + (size_t)mc * HID + s * 64 + h2 * 32;
        uint32_t dA = sA[buf] + (uint32_t)(r * ROWB + h2 * 64);
        #pragma unroll
        for (int q = 0; q < 4; q++) cp16s(dA + 16 * q, srcA + 8 * q);
        const __half* srcB = g_W2h + (size_t)r * HID + s * 64 + h2 * 32;
        uint32_t dB = sB[buf] + (uint32_t)(r * ROWB + h2 * 64);
        #pragma unroll
        for (int q = 0; q < 4; q++) cp16s(dB + 16 * q, srcB + 8 * q);
        CP_COMMIT();
    };

    fill(0, 0);
    for (int s = 0; s < S; s++) {
        int buf = s & 1;
        CP_WAIT0();
        __syncthreads();
        if (s + 1 < S) fill(s + 1, buf ^ 1);
        compute_tile64(acc, sA[buf], sB[buf], wm, wn, lane);
    }

    const int g = lane >> 2, tg = lane & 3;
    #pragma unroll
    for (int mi = 0; mi < 2; mi++) {
        int row0 = rowBase + wm + mi * 16 + g;
        #pragma unroll
        for (int ni = 0; ni < 8; ni++) {
            int col = wn + ni * 8 + tg * 2;
            float b0 = sBias[col], b1 = sBias[col + 1];
            if (row0 < M) {
                size_t o = (size_t)row0 * D + col;
                float v0 = acc[mi][ni][0] + b0 + res[o];
                float v1 = acc[mi][ni][1] + b1 + res[o + 1];
                out[o] = v0; out[o + 1] = v1;
                if (out_h) *(__half2*)(out_h + o) = __floats2half2_rn(v0, v1);
            }
            if (row0 + 8 < M) {
                size_t o = (size_t)(row0 + 8) * D + col;
                float v0 = acc[mi][ni][2] + b0 + res[o];
                float v1 = acc[mi][ni][3] + b1 + res[o + 1];
                out[o] = v0; out[o + 1] = v1;
                if (out_h) *(__half2*)(out_h + o) = __floats2half2_rn(v0, v1);
            }
        }
    }
}

// ---------------- launch -----------------------------------------------------
extern "C" void kernel_launch(void* const* d_in, const int* in_sizes, int n_in,
                              void* d_out, int out_size) {
    const float* nodes = (const float*)d_in[0];
    const float* edges = (const float*)d_in[1];
    const int*   graph = (const int*)  d_in[2];
    const float* nnw   = (const float*)d_in[3];
    const float* nnb   = (const float*)d_in[4];
    const float* enw   = (const float*)d_in[5];
    const float* enb   = (const float*)d_in[6];
    const float* Wn1   = (const float*)d_in[7];
    const float* bn1   = (const float*)d_in[8];
    const float* Wn2   = (const float*)d_in[9];
    const float* bn2   = (const float*)d_in[10];
    const float* We1   = (const float*)d_in[11];
    const float* be1   = (const float*)d_in[12];
    const float* We2   = (const float*)d_in[13];
    const float* be2   = (const float*)d_in[14];

    float* out_nodes = (float*)d_out;
    float* out_edges = out_nodes + (size_t)N_NODES * D;

    cudaFuncSetAttribute(gemm1_hmma<0, KN>, cudaFuncAttributeMaxDynamicSharedMemorySize, G1_SMEM);
    cudaFuncSetAttribute(gemm1_hmma<1, KE>, cudaFuncAttributeMaxDynamicSharedMemorySize, G1_SMEM);
    cudaFuncSetAttribute(gemm2_hmma,        cudaFuncAttributeMaxDynamicSharedMemorySize, G2_SMEM);

    __half* d_no_h;
    int *d_deg_src, *d_deg_dst;
    cudaGetSymbolAddress((void**)&d_no_h,    g_no_h);
    cudaGetSymbolAddress((void**)&d_deg_src, g_deg_src);
    cudaGetSymbolAddress((void**)&d_deg_dst, g_deg_dst);

    // 1) zero msg + degree counts; fused edge pass (scatter + fp16 mirror + stats)
    zero_msg_kernel<<<(N_NODES * D / 4 + 255) / 256, 256>>>();
    cudaMemsetAsync(d_deg_src, 0, N_NODES * sizeof(int));
    cudaMemsetAsync(d_deg_dst, 0, N_NODES * sizeof(int));
    deg_count_kernel<<<(N_EDGES + 255) / 256, 256>>>(graph);
    edge_fused_kernel<<<ESB, 128>>>(edges, graph);

    // 2) node batchnorm stats (also emits nodes_h / msg_h) -> fold into W1
    node_stats_partial<<<NSB, KN>>>(nodes);
    stats_finalize<0><<<KN, FINT>>>(KN, NSB, 1.f / N_NODES, nnw, nnb);
    fold_kernel<<<(HID + 255) / 256, 256>>>(KN, Wn1, bn1);
    w2cvt_kernel<<<(D * HID + 255) / 256, 256>>>(Wn2);

    // 3) node MLP (gemm2 also emits no_h mirror)
    {
        dim3 g1(HID / 128, (N_NODES + 127) / 128);
        gemm1_hmma<0, KN><<<g1, 256, G1_SMEM>>>(nullptr, N_NODES);
        dim3 g2(1, (N_NODES + 127) / 128);
        gemm2_hmma<<<g2, 256, G2_SMEM>>>(bn2, nodes, out_nodes, d_no_h, N_NODES);
    }

    // 4) edge batchnorm stats: cols 0..255 degree-weighted, cols 256..383 from fused pass
    edge_stats_deg<<<ESB, 256>>>(out_nodes);
    stats_finalize<1><<<KE, FINT>>>(KE, ESB, 1.f / N_EDGES, enw, enb);
    fold_kernel<<<(HID + 255) / 256, 256>>>(KE, We1, be1);
    w2cvt_kernel<<<(D * HID + 255) / 256, 256>>>(We2);

    // 5) edge MLP
    {
        dim3 g1(HID / 128, (N_EDGES + 127) / 128);
        gemm1_hmma<1, KE><<<g1, 256, G1_SMEM>>>(graph, N_EDGES);
        dim3 g2(1, (N_EDGES + 127) / 128);
        gemm2_hmma<<<g2, 256, G2_SMEM>>>(be2, edges, out_edges, nullptr, N_EDGES);
    }
}

// round 14
// speedup vs baseline: 1.6317x; 1.0856x over previous
#include <cuda_runtime.h>
#include <cuda_fp16.h>
#include <math.h>
#include <stdint.h>

#define N_NODES 50000
#define N_EDGES 320000
#define D       128
#define HID     512
#define KN      256
#define KE      384
#define EPSV    1e-5f
#define NSB 1024    // node-stats partial blocks
#define ESB 2048    // edge-stats partial blocks
#define FINT 1024   // finalize threads

// ---------------- device scratch (allocation-free: static globals) ----------
__device__ float  g_msg[(size_t)N_NODES * D];           // fp32 scatter target
__device__ __half g_W1hT[(size_t)HID * KE];             // folded W1 [n][k] fp16
__device__ __half g_W2h[(size_t)D * HID];               // W2 [n][k] fp16
__device__ __half g_nodes_h[(size_t)N_NODES * D];       // fp16 mirrors
__device__ __half g_msg_h[(size_t)N_NODES * D];
__device__ __half g_no_h[(size_t)N_NODES * D];          // out_nodes fp16
__device__ __half g_edges_h[(size_t)N_EDGES * D];
__device__ int    g_deg_src[N_NODES];
__device__ int    g_deg_dst[N_NODES];
__device__ float  g_b1p[HID];
__device__ float  g_scale[KE];
__device__ float  g_shift[KE];
__device__ float  g_psum [(size_t)NSB * KN];
__device__ float  g_psq  [(size_t)NSB * KN];
__device__ float  g_epsum[(size_t)ESB * KE];
__device__ float  g_epsq [(size_t)ESB * KE];

// ---------------- helpers ------------------------------------------------
__device__ __forceinline__ float gelu_exact(float x) {
    return 0.5f * x * (1.f + erff(x * 0.70710678118654752f));
}
__device__ __forceinline__ uint32_t smem_u32(const void* p) {
    uint32_t a;
    asm("{ .reg .u64 t; cvta.to.shared.u64 t, %1; cvt.u32.u64 %0, t; }" : "=r"(a) : "l"(p));
    return a;
}
__device__ __forceinline__ void cp16s(uint32_t saddr, const void* g) {
    asm volatile("cp.async.cg.shared.global [%0], [%1], 16;" :: "r"(saddr), "l"(g));
}
#define CP_COMMIT() asm volatile("cp.async.commit_group;" ::: "memory")
#define CP_WAIT0()  asm volatile("cp.async.wait_group 0;" ::: "memory")

__device__ __forceinline__ void ldmx4(uint32_t* r, uint32_t addr) {
    asm volatile("ldmatrix.sync.aligned.m8n8.x4.shared.b16 {%0,%1,%2,%3}, [%4];"
        : "=r"(r[0]), "=r"(r[1]), "=r"(r[2]), "=r"(r[3]) : "r"(addr));
}
__device__ __forceinline__ void mma16(float* c, const uint32_t* a, const uint32_t* b) {
    asm volatile(
        "mma.sync.aligned.m16n8k16.row.col.f32.f16.f16.f32 "
        "{%0,%1,%2,%3}, {%4,%5,%6,%7}, {%8,%9}, {%0,%1,%2,%3};"
        : "+f"(c[0]), "+f"(c[1]), "+f"(c[2]), "+f"(c[3])
        : "r"(a[0]), "r"(a[1]), "r"(a[2]), "r"(a[3]), "r"(b[0]), "r"(b[1]));
}

// k-major tiles: 64 halves/row = 128B + 16B pad = 144B stride
#define ROWB 144
#define ATILE (128 * ROWB)       // 18432 B
#define BTILE (128 * ROWB)       // 18432 B
// Htile: 128 halves/row = 256B + 16B pad = 272B stride (17x16B units -> conflict-free)
#define ROWH 272
#define HTILE (128 * ROWH)       // 34816 B

// ---------------- small kernels ----------------------------------------------
__global__ void zero_msg_kernel() {
    int i = blockIdx.x * blockDim.x + threadIdx.x;
    if (i < N_NODES * D / 4) ((float4*)g_msg)[i] = make_float4(0.f, 0.f, 0.f, 0.f);
}

__global__ void deg_count_kernel(const int* __restrict__ graph) {
    int e = blockIdx.x * blockDim.x + threadIdx.x;
    if (e >= N_EDGES) return;
    atomicAdd(&g_deg_src[__ldg(&graph[e])], 1);
    atomicAdd(&g_deg_dst[__ldg(&graph[N_EDGES + e])], 1);
}

__global__ void edge_fused_kernel(const float* __restrict__ edges,
                                  const int* __restrict__ graph) {
    int t = threadIdx.x;   // 0..127
    float s = 0.f, q = 0.f;
    for (int e = blockIdx.x; e < N_EDGES; e += gridDim.x) {
        int dd = __ldg(&graph[N_EDGES + e]);
        float v = edges[(size_t)e * D + t];
        atomicAdd(&g_msg[(size_t)dd * D + t], v);
        g_edges_h[(size_t)e * D + t] = __float2half_rn(v);
        s += v; q += v * v;
    }
    g_epsum[(size_t)blockIdx.x * KE + 2 * D + t] = s;
    g_epsq [(size_t)blockIdx.x * KE + 2 * D + t] = q;
}

__global__ void node_stats_partial(const float* __restrict__ nodes) {
    int col = threadIdx.x;   // 0..255
    float s = 0.f, q = 0.f;
    for (int r = blockIdx.x; r < N_NODES; r += gridDim.x) {
        float v;
        if (col < D) {
            v = nodes[(size_t)r * D + col];
            g_nodes_h[(size_t)r * D + col] = __float2half_rn(v);
        } else {
            v = g_msg[(size_t)r * D + (col - D)];
            g_msg_h[(size_t)r * D + (col - D)] = __float2half_rn(v);
        }
        s += v; q += v * v;
    }
    g_psum[(size_t)blockIdx.x * KN + col] = s;
    g_psq [(size_t)blockIdx.x * KN + col] = q;
}

__global__ void edge_stats_deg(const float* __restrict__ nodesOut) {
    int t = threadIdx.x;        // 0..255
    int c = t & (D - 1);
    float s = 0.f, q = 0.f;
    for (int v = blockIdx.x; v < N_NODES; v += gridDim.x) {
        float x = nodesOut[(size_t)v * D + c];
        float w = (float)((t < D) ? g_deg_src[v] : g_deg_dst[v]);
        s += w * x;
        q += w * x * x;
    }
    g_epsum[(size_t)blockIdx.x * KE + t] = s;
    g_epsq [(size_t)blockIdx.x * KE + t] = q;
}

template <int EDGE>
__global__ void stats_finalize(int ncols, int nparts, float inv_count,
                               const float* __restrict__ w,
                               const float* __restrict__ b) {
    __shared__ float rs[FINT], rq[FINT];
    int col = blockIdx.x;
    int t = threadIdx.x;
    float s = 0.f, q = 0.f;
    for (int p = t; p < nparts; p += FINT) {
        if (EDGE) {
            s += g_epsum[(size_t)p * ncols + col];
            q += g_epsq [(size_t)p * ncols + col];
        } else {
            s += g_psum[(size_t)p * ncols + col];
            q += g_psq [(size_t)p * ncols + col];
        }
    }
    rs[t] = s; rq[t] = q;
    __syncthreads();
    for (int off = FINT / 2; off > 0; off >>= 1) {
        if (t < off) { rs[t] += rs[t + off]; rq[t] += rq[t + off]; }
        __syncthreads();
    }
    if (t == 0) {
        float mean = rs[0] * inv_count;
        float var  = fmaxf(rq[0] * inv_count - mean * mean, 0.f);
        float sc   = rsqrtf(var + EPSV) * w[col];
        g_scale[col] = sc;
        g_shift[col] = b[col] - mean * sc;
    }
}

__global__ void fold_kernel(int K, const float* __restrict__ W1,
                            const float* __restrict__ b1) {
    int j = blockIdx.x * blockDim.x + threadIdx.x;
    if (j >= HID) return;
    float acc = b1[j];
    for (int k = 0; k < K; k++) {
        float wv = W1[(size_t)k * HID + j];
        acc += g_shift[k] * wv;
        g_W1hT[(size_t)j * K + k] = __float2half_rn(wv * g_scale[k]);
    }
    g_b1p[j] = acc;
}

__global__ void w2cvt_kernel(const float* __restrict__ W2) {
    int i = blockIdx.x * blockDim.x + threadIdx.x;
    if (i >= D * HID) return;
    int n = i >> 9, k = i & 511;
    g_W2h[i] = __float2half_rn(W2[(size_t)k * D + n]);
}

// ---------------- warp-tile compute: 32(m) x 32(n) x 64(k) -------------------
// A smem [m][k] (stride ASTR), B smem [n][k] (stride ROWB); both NON-trans ldmatrix.
template <int ASTR>
__device__ __forceinline__ void compute32(float (&acc)[2][4][4],
                                          uint32_t sA, uint32_t sB,
                                          int wm, int wn, int lane) {
    #pragma unroll
    for (int kk = 0; kk < 64; kk += 16) {
        uint32_t a[2][4];
        #pragma unroll
        for (int mi = 0; mi < 2; mi++) {
            uint32_t addr = sA + (uint32_t)((wm + mi * 16 + (lane & 15)) * ASTR
                                            + kk * 2 + ((lane >> 4) & 1) * 16);
            ldmx4(a[mi], addr);
        }
        uint32_t b[2][4];
        #pragma unroll
        for (int nt = 0; nt < 2; nt++) {
            int nr = wn + nt * 16 + (lane & 7) + ((lane >> 4) & 1) * 8;
            int kof = kk + ((lane >> 3) & 1) * 8;
            ldmx4(b[nt], sB + (uint32_t)(nr * ROWB + kof * 2));
        }
        #pragma unroll
        for (int mi = 0; mi < 2; mi++)
            #pragma unroll
            for (int nt = 0; nt < 2; nt++) {
                mma16(acc[mi][nt * 2 + 0], a[mi], &b[nt][0]);
                mma16(acc[mi][nt * 2 + 1], a[mi], &b[nt][2]);
            }
    }
}

// ---------------- FUSED MLP: out = (gelu(X@W1+b1))@W2 + b2 + res -------------
// MODE 0: K=256, X[m] = [nodes_h[m], msg_h[m]]     (node pass; also emits no_h)
// MODE 1: K=384, X[m] = [no_h[src], no_h[dst], edges_h[m]]   (edge pass)
// CTA: 128 rows x 128 out cols, 512 threads (16 warps, 4m x 4n of 32x32).
// HID processed in 4 chunks of 128; H tile lives in smem (never hits DRAM).
#define FM_SMEM (2 * ATILE + 2 * BTILE + HTILE + 2048 + 512 + 64)

template <int MODE, int K>
__global__ __launch_bounds__(512)
void mlp_fused(const int* __restrict__ graph,
               const float* __restrict__ b2,
               const float* __restrict__ res,
               float* __restrict__ out,
               __half* __restrict__ out_h,
               int M) {
    extern __shared__ __align__(16) char smem[];
    uint32_t base = smem_u32(smem);
    uint32_t sA[2] = { base,              base + ATILE };
    uint32_t sB[2] = { base + 2 * ATILE,  base + 2 * ATILE + BTILE };
    uint32_t hB    = base + 2 * ATILE + 2 * BTILE;
    float* sBias1 = (float*)(smem + 2 * ATILE + 2 * BTILE + HTILE);          // 512
    float* sBias2 = (float*)(smem + 2 * ATILE + 2 * BTILE + HTILE + 2048);   // 128
    __half* hTile = (__half*)(smem + 2 * ATILE + 2 * BTILE);

    const int tid = threadIdx.x, lane = tid & 31, wid = tid >> 5;
    const int wm = (wid & 3) * 32, wn = (wid >> 2) * 32;
    const int rowBase = blockIdx.y * 128;
    const int S1 = K / 64;
    const int g = lane >> 2, tg = lane & 3;

    for (int i = tid; i < HID; i += 512) sBias1[i] = g_b1p[i];
    if (tid < 128) sBias2[tid] = b2[tid];

    // fills: 4 threads per 64-half row, 32B each
    const int rA = tid >> 2, q4 = tid & 3;
    const int mA = rowBase + rA;
    const int mc = (mA < M) ? mA : (M - 1);
    int vsrc = 0, vdst = 0;
    if (MODE == 1) { vsrc = graph[mc]; vdst = graph[N_EDGES + mc]; }

    int aF = 0, aU = 0, bF = 0, bU = 0;

    auto fillA = [&](int kc) {
        int khalf = kc * 64 + q4 * 16;
        int seg = khalf >> 7, l = khalf & 127;
        const __half* p;
        if (MODE == 0) {
            p = (seg == 0 ? g_nodes_h + (size_t)mc * D : g_msg_h + (size_t)mc * D) + l;
        } else {
            p = (seg == 0 ? g_no_h + (size_t)vsrc * D
               : seg == 1 ? g_no_h + (size_t)vdst * D
                          : g_edges_h + (size_t)mc * D) + l;
        }
        uint32_t d = sA[aF & 1] + (uint32_t)(rA * ROWB + q4 * 32);
        cp16s(d, p); cp16s(d + 16, p + 8);
        aF++;
    };
    auto fillB1 = [&](int j, int kc) {
        const __half* p = g_W1hT + (size_t)(j * 128 + rA) * K + kc * 64 + q4 * 16;
        uint32_t d = sB[bF & 1] + (uint32_t)(rA * ROWB + q4 * 32);
        cp16s(d, p); cp16s(d + 16, p + 8);
        bF++;
    };
    auto fillB2 = [&](int j, int kc2) {
        const __half* p = g_W2h + (size_t)rA * HID + j * 128 + kc2 * 64 + q4 * 16;
        uint32_t d = sB[bF & 1] + (uint32_t)(rA * ROWB + q4 * 32);
        cp16s(d, p); cp16s(d + 16, p + 8);
        bF++;
    };

    float o_acc[2][4][4];
    #pragma unroll
    for (int i = 0; i < 2; i++)
        #pragma unroll
        for (int j = 0; j < 4; j++)
            #pragma unroll
            for (int c = 0; c < 4; c++) o_acc[i][j][c] = 0.f;

    fillA(0); fillB1(0, 0); CP_COMMIT();

    for (int j = 0; j < 4; j++) {
        float h_acc[2][4][4];
        #pragma unroll
        for (int i = 0; i < 2; i++)
            #pragma unroll
            for (int jj = 0; jj < 4; jj++)
                #pragma unroll
                for (int c = 0; c < 4; c++) h_acc[i][jj][c] = 0.f;

        // ---- stage 1: h_acc = X @ W1[:, j*128 .. +128] ----
        for (int kc = 0; kc < S1; kc++) {
            CP_WAIT0();
            __syncthreads();
            if (kc + 1 < S1) { fillA(kc + 1); fillB1(j, kc + 1); }
            else             { fillB2(j, 0); }
            CP_COMMIT();
            compute32<ROWB>(h_acc, sA[aU & 1], sB[bU & 1], wm, wn, lane);
            aU++; bU++;
        }

        // ---- stage-1 epilogue: bias + gelu -> Htile (smem) ----
        #pragma unroll
        for (int mi = 0; mi < 2; mi++) {
            int r0 = wm + mi * 16 + g;
            #pragma unroll
            for (int ni = 0; ni < 4; ni++) {
                int c0 = wn + ni * 8 + tg * 2;
                float b0 = sBias1[j * 128 + c0], b1v = sBias1[j * 128 + c0 + 1];
                *(__half2*)((char*)hTile + r0 * ROWH + c0 * 2) =
                    __floats2half2_rn(gelu_exact(h_acc[mi][ni][0] + b0),
                                      gelu_exact(h_acc[mi][ni][1] + b1v));
                *(__half2*)((char*)hTile + (r0 + 8) * ROWH + c0 * 2) =
                    __floats2half2_rn(gelu_exact(h_acc[mi][ni][2] + b0),
                                      gelu_exact(h_acc[mi][ni][3] + b1v));
            }
        }
        __syncthreads();   // Htile visible before ldmatrix

        // ---- stage 2: o_acc += Htile @ W2[j-chunk] ----
        for (int kc2 = 0; kc2 < 2; kc2++) {
            CP_WAIT0();
            __syncthreads();
            if (kc2 == 0)      { fillB2(j, 1); CP_COMMIT(); }
            else if (j + 1 < 4){ fillA(0); fillB1(j + 1, 0); CP_COMMIT(); }
            compute32<ROWH>(o_acc, hB + kc2 * 128, sB[bU & 1], wm, wn, lane);
            bU++;
        }
    }

    // ---- final epilogue: out = o_acc + b2 + res (+ fp16 mirror) ----
    #pragma unroll
    for (int mi = 0; mi < 2; mi++) {
        int row0 = rowBase + wm + mi * 16 + g;
        #pragma unroll
        for (int ni = 0; ni < 4; ni++) {
            int col = wn + ni * 8 + tg * 2;
            float b0 = sBias2[col], b1v = sBias2[col + 1];
            if (row0 < M) {
                size_t o = (size_t)row0 * D + col;
                float v0 = o_acc[mi][ni][0] + b0 + res[o];
                float v1 = o_acc[mi][ni][1] + b1v + res[o + 1];
                out[o] = v0; out[o + 1] = v1;
                if (out_h) *(__half2*)(out_h + o) = __floats2half2_rn(v0, v1);
            }
            if (row0 + 8 < M) {
                size_t o = (size_t)(row0 + 8) * D + col;
                float v0 = o_acc[mi][ni][2] + b0 + res[o];
                float v1 = o_acc[mi][ni][3] + b1v + res[o + 1];
                out[o] = v0; out[o + 1] = v1;
                if (out_h) *(__half2*)(out_h + o) = __floats2half2_rn(v0, v1);
            }
        }
    }
}

// ---------------- launch -----------------------------------------------------
extern "C" void kernel_launch(void* const* d_in, const int* in_sizes, int n_in,
                              void* d_out, int out_size) {
    const float* nodes = (const float*)d_in[0];
    const float* edges = (const float*)d_in[1];
    const int*   graph = (const int*)  d_in[2];
    const float* nnw   = (const float*)d_in[3];
    const float* nnb   = (const float*)d_in[4];
    const float* enw   = (const float*)d_in[5];
    const float* enb   = (const float*)d_in[6];
    const float* Wn1   = (const float*)d_in[7];
    const float* bn1   = (const float*)d_in[8];
    const float* Wn2   = (const float*)d_in[9];
    const float* bn2   = (const float*)d_in[10];
    const float* We1   = (const float*)d_in[11];
    const float* be1   = (const float*)d_in[12];
    const float* We2   = (const float*)d_in[13];
    const float* be2   = (const float*)d_in[14];

    float* out_nodes = (float*)d_out;
    float* out_edges = out_nodes + (size_t)N_NODES * D;

    cudaFuncSetAttribute(mlp_fused<0, KN>, cudaFuncAttributeMaxDynamicSharedMemorySize, FM_SMEM);
    cudaFuncSetAttribute(mlp_fused<1, KE>, cudaFuncAttributeMaxDynamicSharedMemorySize, FM_SMEM);

    __half* d_no_h;
    int *d_deg_src, *d_deg_dst;
    cudaGetSymbolAddress((void**)&d_no_h,    g_no_h);
    cudaGetSymbolAddress((void**)&d_deg_src, g_deg_src);
    cudaGetSymbolAddress((void**)&d_deg_dst, g_deg_dst);

    // 1) zero msg + degree counts; fused edge pass (scatter + fp16 mirror + stats)
    zero_msg_kernel<<<(N_NODES * D / 4 + 255) / 256, 256>>>();
    cudaMemsetAsync(d_deg_src, 0, N_NODES * sizeof(int));
    cudaMemsetAsync(d_deg_dst, 0, N_NODES * sizeof(int));
    deg_count_kernel<<<(N_EDGES + 255) / 256, 256>>>(graph);
    edge_fused_kernel<<<ESB, 128>>>(edges, graph);

    // 2) node batchnorm stats (also emits nodes_h / msg_h) -> fold into W1
    node_stats_partial<<<NSB, KN>>>(nodes);
    stats_finalize<0><<<KN, FINT>>>(KN, NSB, 1.f / N_NODES, nnw, nnb);
    fold_kernel<<<(HID + 255) / 256, 256>>>(KN, Wn1, bn1);
    w2cvt_kernel<<<(D * HID + 255) / 256, 256>>>(Wn2);

    // 3) node MLP (fused; emits no_h mirror)
    {
        dim3 grd(1, (N_NODES + 127) / 128);
        mlp_fused<0, KN><<<grd, 512, FM_SMEM>>>(nullptr, bn2, nodes, out_nodes, d_no_h, N_NODES);
    }

    // 4) edge batchnorm stats: cols 0..255 degree-weighted, cols 256..383 from fused pass
    edge_stats_deg<<<ESB, 256>>>(out_nodes);
    stats_finalize<1><<<KE, FINT>>>(KE, ESB, 1.f / N_EDGES, enw, enb);
    fold_kernel<<<(HID + 255) / 256, 256>>>(KE, We1, be1);
    w2cvt_kernel<<<(D * HID + 255) / 256, 256>>>(We2);

    // 5) edge MLP (fused)
    {
        dim3 grd(1, (N_EDGES + 127) / 128);
        mlp_fused<1, KE><<<grd, 512, FM_SMEM>>>(graph, be2, edges, out_edges, nullptr, N_EDGES);
    }
}

// round 15
// speedup vs baseline: 1.6714x; 1.0243x over previous
#include <cuda_runtime.h>
#include <cuda_fp16.h>
#include <math.h>
#include <stdint.h>

#define N_NODES 50000
#define N_EDGES 320000
#define D       128
#define HID     512
#define KN      256
#define KE      384
#define EPSV    1e-5f
#define NSB 2048    // node-stats partial blocks
#define ESB 2048    // edge-stats (deg) partial blocks
#define E2B 8192    // edge-col partial slots (4 per block)
#define FINT 1024   // finalize threads

// ---------------- device scratch (allocation-free: static globals) ----------
__device__ float  g_msg[(size_t)N_NODES * D];           // fp32 scatter target
__device__ __half g_W1hT[(size_t)HID * KE];             // folded W1 [n][k] fp16
__device__ __half g_W2h[(size_t)D * HID];               // W2 [n][k] fp16
__device__ __half g_nodes_h[(size_t)N_NODES * D];       // fp16 mirrors
__device__ __half g_msg_h[(size_t)N_NODES * D];
__device__ __half g_no_h[(size_t)N_NODES * D];          // out_nodes fp16
__device__ __half g_edges_h[(size_t)N_EDGES * D];
__device__ int    g_deg_src[N_NODES];
__device__ int    g_deg_dst[N_NODES];
__device__ float  g_b1p[HID];
__device__ float  g_scale[KE];
__device__ float  g_shift[KE];
__device__ float  g_psum [(size_t)NSB * KN];            // node stats partials
__device__ float  g_psq  [(size_t)NSB * KN];
__device__ float  g_epsum[(size_t)ESB * KE];            // edge deg-weighted partials (cols 0..255)
__device__ float  g_epsq [(size_t)ESB * KE];
__device__ float  g_e2sum[(size_t)E2B * D];             // edge col partials (cols 256..383)
__device__ float  g_e2sq [(size_t)E2B * D];

// ---------------- helpers ------------------------------------------------
__device__ __forceinline__ float gelu_exact(float x) {
    return 0.5f * x * (1.f + erff(x * 0.70710678118654752f));
}
__device__ __forceinline__ uint32_t smem_u32(const void* p) {
    uint32_t a;
    asm("{ .reg .u64 t; cvta.to.shared.u64 t, %1; cvt.u32.u64 %0, t; }" : "=r"(a) : "l"(p));
    return a;
}
__device__ __forceinline__ void cp16s(uint32_t saddr, const void* g) {
    asm volatile("cp.async.cg.shared.global [%0], [%1], 16;" :: "r"(saddr), "l"(g));
}
#define CP_COMMIT() asm volatile("cp.async.commit_group;" ::: "memory")
#define CP_WAIT0()  asm volatile("cp.async.wait_group 0;" ::: "memory")

__device__ __forceinline__ void ldmx4(uint32_t* r, uint32_t addr) {
    asm volatile("ldmatrix.sync.aligned.m8n8.x4.shared.b16 {%0,%1,%2,%3}, [%4];"
        : "=r"(r[0]), "=r"(r[1]), "=r"(r[2]), "=r"(r[3]) : "r"(addr));
}
__device__ __forceinline__ void mma16(float* c, const uint32_t* a, const uint32_t* b) {
    asm volatile(
        "mma.sync.aligned.m16n8k16.row.col.f32.f16.f16.f32 "
        "{%0,%1,%2,%3}, {%4,%5,%6,%7}, {%8,%9}, {%0,%1,%2,%3};"
        : "+f"(c[0]), "+f"(c[1]), "+f"(c[2]), "+f"(c[3])
        : "r"(a[0]), "r"(a[1]), "r"(a[2]), "r"(a[3]), "r"(b[0]), "r"(b[1]));
}
__device__ __forceinline__ void red4(float* gdst, float4 v) {
    asm volatile("red.global.add.v4.f32 [%0], {%1,%2,%3,%4};"
        :: "l"(gdst), "f"(v.x), "f"(v.y), "f"(v.z), "f"(v.w) : "memory");
}

// k-major tiles: 64 halves/row = 128B + 16B pad = 144B stride
#define ROWB 144
#define ATILE (128 * ROWB)       // 18432 B
#define BTILE (128 * ROWB)       // 18432 B
// Htile: 128 halves/row = 256B + 16B pad = 272B stride
#define ROWH 272
#define HTILE (128 * ROWH)       // 34816 B

// ---------------- small kernels ----------------------------------------------
__global__ void zero_msg_kernel() {
    int i = blockIdx.x * blockDim.x + threadIdx.x;
    if (i < N_NODES * D / 4) ((float4*)g_msg)[i] = make_float4(0.f, 0.f, 0.f, 0.f);
}

// ONE pass over edges: vector-red scatter + fp16 mirror + col stats + degree counts.
// 128 threads = 4 edges x 32 lanes; lane owns cols lane*4..+3 (fixed across iters).
__global__ void edge_fused_kernel(const float* __restrict__ edges,
                                  const int* __restrict__ graph) {
    int t = threadIdx.x;
    int sub = t >> 5, lane = t & 31;
    int p = blockIdx.x * 4 + sub;                  // partial slot, fixed
    float4 s = make_float4(0.f, 0.f, 0.f, 0.f);
    float4 q = make_float4(0.f, 0.f, 0.f, 0.f);
    for (int e = blockIdx.x * 4 + sub; e < N_EDGES; e += gridDim.x * 4) {
        int dd = __ldg(&graph[N_EDGES + e]);
        float4 v = *(const float4*)(edges + (size_t)e * D + lane * 4);
        red4(g_msg + (size_t)dd * D + lane * 4, v);
        __half2 h0 = __floats2half2_rn(v.x, v.y);
        __half2 h1 = __floats2half2_rn(v.z, v.w);
        *(uint2*)(g_edges_h + (size_t)e * D + lane * 4) =
            make_uint2(*(uint32_t*)&h0, *(uint32_t*)&h1);
        s.x += v.x; s.y += v.y; s.z += v.z; s.w += v.w;
        q.x += v.x * v.x; q.y += v.y * v.y; q.z += v.z * v.z; q.w += v.w * v.w;
        if (lane == 0) {
            atomicAdd(&g_deg_dst[dd], 1);
            atomicAdd(&g_deg_src[__ldg(&graph[e])], 1);
        }
    }
    int c = lane * 4;
    *(float4*)(g_e2sum + (size_t)p * D + c) = s;
    *(float4*)(g_e2sq  + (size_t)p * D + c) = q;
}

// node stats over [nodes | msg] + write fp16 mirrors
__global__ void node_stats_partial(const float* __restrict__ nodes) {
    int col = threadIdx.x;   // 0..255
    float s = 0.f, q = 0.f;
    for (int r = blockIdx.x; r < N_NODES; r += gridDim.x) {
        float v;
        if (col < D) {
            v = nodes[(size_t)r * D + col];
            g_nodes_h[(size_t)r * D + col] = __float2half_rn(v);
        } else {
            v = g_msg[(size_t)r * D + (col - D)];
            g_msg_h[(size_t)r * D + (col - D)] = __float2half_rn(v);
        }
        s += v; q += v * v;
    }
    g_psum[(size_t)blockIdx.x * KN + col] = s;
    g_psq [(size_t)blockIdx.x * KN + col] = q;
}

// edge-stats cols 0..255 via degree weighting over out_nodes
__global__ void edge_stats_deg(const float* __restrict__ nodesOut) {
    int t = threadIdx.x;        // 0..255
    int c = t & (D - 1);
    float s = 0.f, q = 0.f;
    for (int v = blockIdx.x; v < N_NODES; v += gridDim.x) {
        float x = nodesOut[(size_t)v * D + c];
        float w = (float)((t < D) ? g_deg_src[v] : g_deg_dst[v]);
        s += w * x;
        q += w * x * x;
    }
    g_epsum[(size_t)blockIdx.x * KE + t] = s;
    g_epsq [(size_t)blockIdx.x * KE + t] = q;
}

// finalize. EDGE=0: node partials (stride KN, nparts). EDGE=1: col<256 from
// deg-weighted partials (ESB x KE), col>=256 from edge col partials (E2B x D).
template <int EDGE>
__global__ void stats_finalize(int ncols, int nparts, float inv_count,
                               const float* __restrict__ w,
                               const float* __restrict__ b) {
    __shared__ float rs[FINT], rq[FINT];
    int col = blockIdx.x;
    int t = threadIdx.x;
    float s = 0.f, q = 0.f;
    if (EDGE) {
        if (col < 2 * D) {
            for (int p = t; p < ESB; p += FINT) {
                s += g_epsum[(size_t)p * KE + col];
                q += g_epsq [(size_t)p * KE + col];
            }
        } else {
            int c2 = col - 2 * D;
            for (int p = t; p < E2B; p += FINT) {
                s += g_e2sum[(size_t)p * D + c2];
                q += g_e2sq [(size_t)p * D + c2];
            }
        }
    } else {
        for (int p = t; p < nparts; p += FINT) {
            s += g_psum[(size_t)p * ncols + col];
            q += g_psq [(size_t)p * ncols + col];
        }
    }
    rs[t] = s; rq[t] = q;
    __syncthreads();
    for (int off = FINT / 2; off > 0; off >>= 1) {
        if (t < off) { rs[t] += rs[t + off]; rq[t] += rq[t + off]; }
        __syncthreads();
    }
    if (t == 0) {
        float mean = rs[0] * inv_count;
        float var  = fmaxf(rq[0] * inv_count - mean * mean, 0.f);
        float sc   = rsqrtf(var + EPSV) * w[col];
        g_scale[col] = sc;
        g_shift[col] = b[col] - mean * sc;
    }
}

__global__ void fold_kernel(int K, const float* __restrict__ W1,
                            const float* __restrict__ b1) {
    int j = blockIdx.x * blockDim.x + threadIdx.x;
    if (j >= HID) return;
    float acc = b1[j];
    for (int k = 0; k < K; k++) {
        float wv = W1[(size_t)k * HID + j];
        acc += g_shift[k] * wv;
        g_W1hT[(size_t)j * K + k] = __float2half_rn(wv * g_scale[k]);
    }
    g_b1p[j] = acc;
}

__global__ void w2cvt_kernel(const float* __restrict__ W2) {
    int i = blockIdx.x * blockDim.x + threadIdx.x;
    if (i >= D * HID) return;
    int n = i >> 9, k = i & 511;
    g_W2h[i] = __float2half_rn(W2[(size_t)k * D + n]);
}

// ---------------- warp-tile compute: 32(m) x 32(n) x 64(k) -------------------
template <int ASTR>
__device__ __forceinline__ void compute32(float (&acc)[2][4][4],
                                          uint32_t sA, uint32_t sB,
                                          int wm, int wn, int lane) {
    #pragma unroll
    for (int kk = 0; kk < 64; kk += 16) {
        uint32_t a[2][4];
        #pragma unroll
        for (int mi = 0; mi < 2; mi++) {
            uint32_t addr = sA + (uint32_t)((wm + mi * 16 + (lane & 15)) * ASTR
                                            + kk * 2 + ((lane >> 4) & 1) * 16);
            ldmx4(a[mi], addr);
        }
        uint32_t b[2][4];
        #pragma unroll
        for (int nt = 0; nt < 2; nt++) {
            int nr = wn + nt * 16 + (lane & 7) + ((lane >> 4) & 1) * 8;
            int kof = kk + ((lane >> 3) & 1) * 8;
            ldmx4(b[nt], sB + (uint32_t)(nr * ROWB + kof * 2));
        }
        #pragma unroll
        for (int mi = 0; mi < 2; mi++)
            #pragma unroll
            for (int nt = 0; nt < 2; nt++) {
                mma16(acc[mi][nt * 2 + 0], a[mi], &b[nt][0]);
                mma16(acc[mi][nt * 2 + 1], a[mi], &b[nt][2]);
            }
    }
}

// ---------------- FUSED MLP: out = (gelu(X@W1+b1))@W2 + b2 + res -------------
#define FM_SMEM (2 * ATILE + 2 * BTILE + HTILE + 2048 + 512 + 64)

template <int MODE, int K>
__global__ __launch_bounds__(512)
void mlp_fused(const int* __restrict__ graph,
               const float* __restrict__ b2,
               const float* __restrict__ res,
               float* __restrict__ out,
               __half* __restrict__ out_h,
               int M) {
    extern __shared__ __align__(16) char smem[];
    uint32_t base = smem_u32(smem);
    uint32_t sA[2] = { base,              base + ATILE };
    uint32_t sB[2] = { base + 2 * ATILE,  base + 2 * ATILE + BTILE };
    uint32_t hB    = base + 2 * ATILE + 2 * BTILE;
    float* sBias1 = (float*)(smem + 2 * ATILE + 2 * BTILE + HTILE);
    float* sBias2 = (float*)(smem + 2 * ATILE + 2 * BTILE + HTILE + 2048);
    __half* hTile = (__half*)(smem + 2 * ATILE + 2 * BTILE);

    const int tid = threadIdx.x, lane = tid & 31, wid = tid >> 5;
    const int wm = (wid & 3) * 32, wn = (wid >> 2) * 32;
    const int rowBase = blockIdx.y * 128;
    const int S1 = K / 64;
    const int g = lane >> 2, tg = lane & 3;

    for (int i = tid; i < HID; i += 512) sBias1[i] = g_b1p[i];
    if (tid < 128) sBias2[tid] = b2[tid];

    const int rA = tid >> 2, q4 = tid & 3;
    const int mA = rowBase + rA;
    const int mc = (mA < M) ? mA : (M - 1);
    int vsrc = 0, vdst = 0;
    if (MODE == 1) { vsrc = graph[mc]; vdst = graph[N_EDGES + mc]; }

    int aF = 0, aU = 0, bF = 0, bU = 0;

    auto fillA = [&](int kc) {
        int khalf = kc * 64 + q4 * 16;
        int seg = khalf >> 7, l = khalf & 127;
        const __half* p;
        if (MODE == 0) {
            p = (seg == 0 ? g_nodes_h + (size_t)mc * D : g_msg_h + (size_t)mc * D) + l;
        } else {
            p = (seg == 0 ? g_no_h + (size_t)vsrc * D
               : seg == 1 ? g_no_h + (size_t)vdst * D
                          : g_edges_h + (size_t)mc * D) + l;
        }
        uint32_t d = sA[aF & 1] + (uint32_t)(rA * ROWB + q4 * 32);
        cp16s(d, p); cp16s(d + 16, p + 8);
        aF++;
    };
    auto fillB1 = [&](int j, int kc) {
        const __half* p = g_W1hT + (size_t)(j * 128 + rA) * K + kc * 64 + q4 * 16;
        uint32_t d = sB[bF & 1] + (uint32_t)(rA * ROWB + q4 * 32);
        cp16s(d, p); cp16s(d + 16, p + 8);
        bF++;
    };
    auto fillB2 = [&](int j, int kc2) {
        const __half* p = g_W2h + (size_t)rA * HID + j * 128 + kc2 * 64 + q4 * 16;
        uint32_t d = sB[bF & 1] + (uint32_t)(rA * ROWB + q4 * 32);
        cp16s(d, p); cp16s(d + 16, p + 8);
        bF++;
    };

    float o_acc[2][4][4];
    #pragma unroll
    for (int i = 0; i < 2; i++)
        #pragma unroll
        for (int j = 0; j < 4; j++)
            #pragma unroll
            for (int c = 0; c < 4; c++) o_acc[i][j][c] = 0.f;

    fillA(0); fillB1(0, 0); CP_COMMIT();

    for (int j = 0; j < 4; j++) {
        float h_acc[2][4][4];
        #pragma unroll
        for (int i = 0; i < 2; i++)
            #pragma unroll
            for (int jj = 0; jj < 4; jj++)
                #pragma unroll
                for (int c = 0; c < 4; c++) h_acc[i][jj][c] = 0.f;

        for (int kc = 0; kc < S1; kc++) {
            CP_WAIT0();
            __syncthreads();
            if (kc + 1 < S1) { fillA(kc + 1); fillB1(j, kc + 1); }
            else             { fillB2(j, 0); }
            CP_COMMIT();
            compute32<ROWB>(h_acc, sA[aU & 1], sB[bU & 1], wm, wn, lane);
            aU++; bU++;
        }

        #pragma unroll
        for (int mi = 0; mi < 2; mi++) {
            int r0 = wm + mi * 16 + g;
            #pragma unroll
            for (int ni = 0; ni < 4; ni++) {
                int c0 = wn + ni * 8 + tg * 2;
                float b0 = sBias1[j * 128 + c0], b1v = sBias1[j * 128 + c0 + 1];
                *(__half2*)((char*)hTile + r0 * ROWH + c0 * 2) =
                    __floats2half2_rn(gelu_exact(h_acc[mi][ni][0] + b0),
                                      gelu_exact(h_acc[mi][ni][1] + b1v));
                *(__half2*)((char*)hTile + (r0 + 8) * ROWH + c0 * 2) =
                    __floats2half2_rn(gelu_exact(h_acc[mi][ni][2] + b0),
                                      gelu_exact(h_acc[mi][ni][3] + b1v));
            }
        }
        __syncthreads();

        for (int kc2 = 0; kc2 < 2; kc2++) {
            CP_WAIT0();
            __syncthreads();
            if (kc2 == 0)      { fillB2(j, 1); CP_COMMIT(); }
            else if (j + 1 < 4){ fillA(0); fillB1(j + 1, 0); CP_COMMIT(); }
            compute32<ROWH>(o_acc, hB + kc2 * 128, sB[bU & 1], wm, wn, lane);
            bU++;
        }
    }

    #pragma unroll
    for (int mi = 0; mi < 2; mi++) {
        int row0 = rowBase + wm + mi * 16 + g;
        #pragma unroll
        for (int ni = 0; ni < 4; ni++) {
            int col = wn + ni * 8 + tg * 2;
            float b0 = sBias2[col], b1v = sBias2[col + 1];
            if (row0 < M) {
                size_t o = (size_t)row0 * D + col;
                float v0 = o_acc[mi][ni][0] + b0 + res[o];
                float v1 = o_acc[mi][ni][1] + b1v + res[o + 1];
                out[o] = v0; out[o + 1] = v1;
                if (out_h) *(__half2*)(out_h + o) = __floats2half2_rn(v0, v1);
            }
            if (row0 + 8 < M) {
                size_t o = (size_t)(row0 + 8) * D + col;
                float v0 = o_acc[mi][ni][2] + b0 + res[o];
                float v1 = o_acc[mi][ni][3] + b1v + res[o + 1];
                out[o] = v0; out[o + 1] = v1;
                if (out_h) *(__half2*)(out_h + o) = __floats2half2_rn(v0, v1);
            }
        }
    }
}

// ---------------- launch -----------------------------------------------------
extern "C" void kernel_launch(void* const* d_in, const int* in_sizes, int n_in,
                              void* d_out, int out_size) {
    const float* nodes = (const float*)d_in[0];
    const float* edges = (const float*)d_in[1];
    const int*   graph = (const int*)  d_in[2];
    const float* nnw   = (const float*)d_in[3];
    const float* nnb   = (const float*)d_in[4];
    const float* enw   = (const float*)d_in[5];
    const float* enb   = (const float*)d_in[6];
    const float* Wn1   = (const float*)d_in[7];
    const float* bn1   = (const float*)d_in[8];
    const float* Wn2   = (const float*)d_in[9];
    const float* bn2   = (const float*)d_in[10];
    const float* We1   = (const float*)d_in[11];
    const float* be1   = (const float*)d_in[12];
    const float* We2   = (const float*)d_in[13];
    const float* be2   = (const float*)d_in[14];

    float* out_nodes = (float*)d_out;
    float* out_edges = out_nodes + (size_t)N_NODES * D;

    cudaFuncSetAttribute(mlp_fused<0, KN>, cudaFuncAttributeMaxDynamicSharedMemorySize, FM_SMEM);
    cudaFuncSetAttribute(mlp_fused<1, KE>, cudaFuncAttributeMaxDynamicSharedMemorySize, FM_SMEM);

    __half* d_no_h;
    int *d_deg_src, *d_deg_dst;
    cudaGetSymbolAddress((void**)&d_no_h,    g_no_h);
    cudaGetSymbolAddress((void**)&d_deg_src, g_deg_src);
    cudaGetSymbolAddress((void**)&d_deg_dst, g_deg_dst);

    // 1) zero msg + deg; single fused edge pass (vector-red scatter + mirror + stats + deg)
    zero_msg_kernel<<<(N_NODES * D / 4 + 255) / 256, 256>>>();
    cudaMemsetAsync(d_deg_src, 0, N_NODES * sizeof(int));
    cudaMemsetAsync(d_deg_dst, 0, N_NODES * sizeof(int));
    edge_fused_kernel<<<ESB, 128>>>(edges, graph);

    // 2) node batchnorm stats (emits nodes_h / msg_h) -> fold into W1
    node_stats_partial<<<NSB, KN>>>(nodes);
    stats_finalize<0><<<KN, FINT>>>(KN, NSB, 1.f / N_NODES, nnw, nnb);
    fold_kernel<<<(HID + 255) / 256, 256>>>(KN, Wn1, bn1);
    w2cvt_kernel<<<(D * HID + 255) / 256, 256>>>(Wn2);

    // 3) node MLP (fused; emits no_h mirror)
    {
        dim3 grd(1, (N_NODES + 127) / 128);
        mlp_fused<0, KN><<<grd, 512, FM_SMEM>>>(nullptr, bn2, nodes, out_nodes, d_no_h, N_NODES);
    }

    // 4) edge batchnorm stats: cols 0..255 degree-weighted, cols 256..383 from fused pass
    edge_stats_deg<<<ESB, 256>>>(out_nodes);
    stats_finalize<1><<<KE, FINT>>>(KE, 0, 1.f / N_EDGES, enw, enb);
    fold_kernel<<<(HID + 255) / 256, 256>>>(KE, We1, be1);
    w2cvt_kernel<<<(D * HID + 255) / 256, 256>>>(We2);

    // 5) edge MLP (fused)
    {
        dim3 grd(1, (N_EDGES + 127) / 128);
        mlp_fused<1, KE><<<grd, 512, FM_SMEM>>>(graph, be2, edges, out_edges, nullptr, N_EDGES);
    }
}

// round 16
// speedup vs baseline: 1.6821x; 1.0064x over previous
#include <cuda_runtime.h>
#include <cuda_fp16.h>
#include <math.h>
#include <stdint.h>

#define N_NODES 50000
#define N_EDGES 320000
#define D       128
#define HID     512
#define KN      256
#define KE      384
#define EPSV    1e-5f
#define NSB 2048    // node-stats partial blocks
#define ESB 2048    // edge-stats (deg) partial blocks
#define E2B 8192    // edge-col partial slots (4 per block)
#define FINT 1024   // finalize threads

// ---------------- device scratch (allocation-free: static globals) ----------
__device__ float  g_msg[(size_t)N_NODES * D];           // fp32 scatter target
__device__ __half g_W1hT[(size_t)HID * KE];             // folded W1 [n][k] fp16
__device__ __half g_W2h[(size_t)D * HID];               // W2 [n][k] fp16
__device__ __half g_nodes_h[(size_t)N_NODES * D];       // fp16 mirrors
__device__ __half g_msg_h[(size_t)N_NODES * D];
__device__ __half g_no_h[(size_t)N_NODES * D];          // out_nodes fp16
__device__ __half g_edges_h[(size_t)N_EDGES * D];
__device__ int    g_deg_src[N_NODES];
__device__ int    g_deg_dst[N_NODES];
__device__ float  g_b1p[HID];
__device__ float  g_scale[KE];
__device__ float  g_shift[KE];
__device__ float  g_psum [(size_t)NSB * KN];            // node stats partials
__device__ float  g_psq  [(size_t)NSB * KN];
__device__ float  g_epsum[(size_t)ESB * KE];            // edge deg-weighted partials (cols 0..255)
__device__ float  g_epsq [(size_t)ESB * KE];
__device__ float  g_e2sum[(size_t)E2B * D];             // edge col partials (cols 256..383)
__device__ float  g_e2sq [(size_t)E2B * D];

// ---------------- helpers ------------------------------------------------
__device__ __forceinline__ float gelu_exact(float x) {
    return 0.5f * x * (1.f + erff(x * 0.70710678118654752f));
}
__device__ __forceinline__ uint32_t smem_u32(const void* p) {
    uint32_t a;
    asm("{ .reg .u64 t; cvta.to.shared.u64 t, %1; cvt.u32.u64 %0, t; }" : "=r"(a) : "l"(p));
    return a;
}
__device__ __forceinline__ void cp16s(uint32_t saddr, const void* g) {
    asm volatile("cp.async.cg.shared.global [%0], [%1], 16;" :: "r"(saddr), "l"(g));
}
#define CP_COMMIT() asm volatile("cp.async.commit_group;" ::: "memory")
#define CP_WAIT0()  asm volatile("cp.async.wait_group 0;" ::: "memory")

__device__ __forceinline__ void ldmx4(uint32_t* r, uint32_t addr) {
    asm volatile("ldmatrix.sync.aligned.m8n8.x4.shared.b16 {%0,%1,%2,%3}, [%4];"
        : "=r"(r[0]), "=r"(r[1]), "=r"(r[2]), "=r"(r[3]) : "r"(addr));
}
__device__ __forceinline__ void mma16(float* c, const uint32_t* a, const uint32_t* b) {
    asm volatile(
        "mma.sync.aligned.m16n8k16.row.col.f32.f16.f16.f32 "
        "{%0,%1,%2,%3}, {%4,%5,%6,%7}, {%8,%9}, {%0,%1,%2,%3};"
        : "+f"(c[0]), "+f"(c[1]), "+f"(c[2]), "+f"(c[3])
        : "r"(a[0]), "r"(a[1]), "r"(a[2]), "r"(a[3]), "r"(b[0]), "r"(b[1]));
}
__device__ __forceinline__ void red4(float* gdst, float4 v) {
    asm volatile("red.global.add.v4.f32 [%0], {%1,%2,%3,%4};"
        :: "l"(gdst), "f"(v.x), "f"(v.y), "f"(v.z), "f"(v.w) : "memory");
}

// k-major tiles: 64 halves/row = 128B + 16B pad = 144B stride
#define ROWB 144
#define ATILE (128 * ROWB)       // 18432 B
#define BTILE (128 * ROWB)       // 18432 B
// Htile: 128 halves/row = 256B + 16B pad = 272B stride
#define ROWH 272
#define HTILE (128 * ROWH)       // 34816 B

// ---------------- small kernels ----------------------------------------------
// One init kernel: zero msg (1.6M fl4) + both degree arrays.
__global__ void init_kernel() {
    int i = blockIdx.x * blockDim.x + threadIdx.x;
    if (i < N_NODES * D / 4) ((float4*)g_msg)[i] = make_float4(0.f, 0.f, 0.f, 0.f);
    if (i < N_NODES) { g_deg_src[i] = 0; g_deg_dst[i] = 0; }
}

// ONE pass over edges: vector-red scatter + fp16 mirror + col stats + degree counts.
__global__ void edge_fused_kernel(const float* __restrict__ edges,
                                  const int* __restrict__ graph) {
    int t = threadIdx.x;
    int sub = t >> 5, lane = t & 31;
    int p = blockIdx.x * 4 + sub;                  // partial slot, fixed
    float4 s = make_float4(0.f, 0.f, 0.f, 0.f);
    float4 q = make_float4(0.f, 0.f, 0.f, 0.f);
    for (int e = blockIdx.x * 4 + sub; e < N_EDGES; e += gridDim.x * 4) {
        int dd = __ldg(&graph[N_EDGES + e]);
        float4 v = *(const float4*)(edges + (size_t)e * D + lane * 4);
        red4(g_msg + (size_t)dd * D + lane * 4, v);
        __half2 h0 = __floats2half2_rn(v.x, v.y);
        __half2 h1 = __floats2half2_rn(v.z, v.w);
        *(uint2*)(g_edges_h + (size_t)e * D + lane * 4) =
            make_uint2(*(uint32_t*)&h0, *(uint32_t*)&h1);
        s.x += v.x; s.y += v.y; s.z += v.z; s.w += v.w;
        q.x += v.x * v.x; q.y += v.y * v.y; q.z += v.z * v.z; q.w += v.w * v.w;
        if (lane == 0) {
            atomicAdd(&g_deg_dst[dd], 1);
            atomicAdd(&g_deg_src[__ldg(&graph[e])], 1);
        }
    }
    int c = lane * 4;
    *(float4*)(g_e2sum + (size_t)p * D + c) = s;
    *(float4*)(g_e2sq  + (size_t)p * D + c) = q;
}

// node stats over [nodes | msg] + write fp16 mirrors
__global__ void node_stats_partial(const float* __restrict__ nodes) {
    int col = threadIdx.x;   // 0..255
    float s = 0.f, q = 0.f;
    for (int r = blockIdx.x; r < N_NODES; r += gridDim.x) {
        float v;
        if (col < D) {
            v = nodes[(size_t)r * D + col];
            g_nodes_h[(size_t)r * D + col] = __float2half_rn(v);
        } else {
            v = g_msg[(size_t)r * D + (col - D)];
            g_msg_h[(size_t)r * D + (col - D)] = __float2half_rn(v);
        }
        s += v; q += v * v;
    }
    g_psum[(size_t)blockIdx.x * KN + col] = s;
    g_psq [(size_t)blockIdx.x * KN + col] = q;
}

// edge-stats cols 0..255 via degree weighting over out_nodes
__global__ void edge_stats_deg(const float* __restrict__ nodesOut) {
    int t = threadIdx.x;        // 0..255
    int c = t & (D - 1);
    float s = 0.f, q = 0.f;
    for (int v = blockIdx.x; v < N_NODES; v += gridDim.x) {
        float x = nodesOut[(size_t)v * D + c];
        float w = (float)((t < D) ? g_deg_src[v] : g_deg_dst[v]);
        s += w * x;
        q += w * x * x;
    }
    g_epsum[(size_t)blockIdx.x * KE + t] = s;
    g_epsq [(size_t)blockIdx.x * KE + t] = q;
}

// finalize. EDGE=0: node partials. EDGE=1: col<256 deg-weighted, col>=256 col partials.
template <int EDGE>
__global__ void stats_finalize(int ncols, int nparts, float inv_count,
                               const float* __restrict__ w,
                               const float* __restrict__ b) {
    __shared__ float rs[FINT], rq[FINT];
    int col = blockIdx.x;
    int t = threadIdx.x;
    float s = 0.f, q = 0.f;
    if (EDGE) {
        if (col < 2 * D) {
            for (int p = t; p < ESB; p += FINT) {
                s += g_epsum[(size_t)p * KE + col];
                q += g_epsq [(size_t)p * KE + col];
            }
        } else {
            int c2 = col - 2 * D;
            for (int p = t; p < E2B; p += FINT) {
                s += g_e2sum[(size_t)p * D + c2];
                q += g_e2sq [(size_t)p * D + c2];
            }
        }
    } else {
        for (int p = t; p < nparts; p += FINT) {
            s += g_psum[(size_t)p * ncols + col];
            q += g_psq [(size_t)p * ncols + col];
        }
    }
    rs[t] = s; rq[t] = q;
    __syncthreads();
    for (int off = FINT / 2; off > 0; off >>= 1) {
        if (t < off) { rs[t] += rs[t + off]; rq[t] += rq[t + off]; }
        __syncthreads();
    }
    if (t == 0) {
        float mean = rs[0] * inv_count;
        float var  = fmaxf(rq[0] * inv_count - mean * mean, 0.f);
        float sc   = rsqrtf(var + EPSV) * w[col];
        g_scale[col] = sc;
        g_shift[col] = b[col] - mean * sc;
    }
}

// Merged: blocks 0..1 fold BN into W1 (transposed fp16); blocks 2..257 convert W2.
__global__ void fold_w2cvt_kernel(int K, const float* __restrict__ W1,
                                  const float* __restrict__ b1,
                                  const float* __restrict__ W2) {
    if (blockIdx.x < 2) {
        int j = blockIdx.x * 256 + threadIdx.x;      // 0..511
        float acc = b1[j];
        for (int k = 0; k < K; k++) {
            float wv = W1[(size_t)k * HID + j];
            acc += g_shift[k] * wv;
            g_W1hT[(size_t)j * K + k] = __float2half_rn(wv * g_scale[k]);
        }
        g_b1p[j] = acc;
    } else {
        int i = (blockIdx.x - 2) * 256 + threadIdx.x;  // 0..65535
        int n = i >> 9, k = i & 511;
        g_W2h[i] = __float2half_rn(W2[(size_t)k * D + n]);
    }
}

// ---------------- warp-tile compute: 32(m) x 32(n) x 64(k) -------------------
template <int ASTR>
__device__ __forceinline__ void compute32(float (&acc)[2][4][4],
                                          uint32_t sA, uint32_t sB,
                                          int wm, int wn, int lane) {
    #pragma unroll
    for (int kk = 0; kk < 64; kk += 16) {
        uint32_t a[2][4];
        #pragma unroll
        for (int mi = 0; mi < 2; mi++) {
            uint32_t addr = sA + (uint32_t)((wm + mi * 16 + (lane & 15)) * ASTR
                                            + kk * 2 + ((lane >> 4) & 1) * 16);
            ldmx4(a[mi], addr);
        }
        uint32_t b[2][4];
        #pragma unroll
        for (int nt = 0; nt < 2; nt++) {
            int nr = wn + nt * 16 + (lane & 7) + ((lane >> 4) & 1) * 8;
            int kof = kk + ((lane >> 3) & 1) * 8;
            ldmx4(b[nt], sB + (uint32_t)(nr * ROWB + kof * 2));
        }
        #pragma unroll
        for (int mi = 0; mi < 2; mi++)
            #pragma unroll
            for (int nt = 0; nt < 2; nt++) {
                mma16(acc[mi][nt * 2 + 0], a[mi], &b[nt][0]);
                mma16(acc[mi][nt * 2 + 1], a[mi], &b[nt][2]);
            }
    }
}

// ---------------- FUSED MLP: out = (gelu(X@W1+b1))@W2 + b2 + res -------------
#define FM_SMEM (2 * ATILE + 2 * BTILE + HTILE + 2048 + 512 + 64)

template <int MODE, int K>
__global__ __launch_bounds__(512)
void mlp_fused(const int* __restrict__ graph,
               const float* __restrict__ b2,
               const float* __restrict__ res,
               float* __restrict__ out,
               __half* __restrict__ out_h,
               int M) {
    extern __shared__ __align__(16) char smem[];
    uint32_t base = smem_u32(smem);
    uint32_t sA[2] = { base,              base + ATILE };
    uint32_t sB[2] = { base + 2 * ATILE,  base + 2 * ATILE + BTILE };
    uint32_t hB    = base + 2 * ATILE + 2 * BTILE;
    float* sBias1 = (float*)(smem + 2 * ATILE + 2 * BTILE + HTILE);
    float* sBias2 = (float*)(smem + 2 * ATILE + 2 * BTILE + HTILE + 2048);
    __half* hTile = (__half*)(smem + 2 * ATILE + 2 * BTILE);

    const int tid = threadIdx.x, lane = tid & 31, wid = tid >> 5;
    const int wm = (wid & 3) * 32, wn = (wid >> 2) * 32;
    const int rowBase = blockIdx.y * 128;
    const int S1 = K / 64;
    const int g = lane >> 2, tg = lane & 3;

    for (int i = tid; i < HID; i += 512) sBias1[i] = g_b1p[i];
    if (tid < 128) sBias2[tid] = b2[tid];

    const int rA = tid >> 2, q4 = tid & 3;
    const int mA = rowBase + rA;
    const int mc = (mA < M) ? mA : (M - 1);
    int vsrc = 0, vdst = 0;
    if (MODE == 1) { vsrc = graph[mc]; vdst = graph[N_EDGES + mc]; }

    int aF = 0, aU = 0, bF = 0, bU = 0;

    auto fillA = [&](int kc) {
        int khalf = kc * 64 + q4 * 16;
        int seg = khalf >> 7, l = khalf & 127;
        const __half* p;
        if (MODE == 0) {
            p = (seg == 0 ? g_nodes_h + (size_t)mc * D : g_msg_h + (size_t)mc * D) + l;
        } else {
            p = (seg == 0 ? g_no_h + (size_t)vsrc * D
               : seg == 1 ? g_no_h + (size_t)vdst * D
                          : g_edges_h + (size_t)mc * D) + l;
        }
        uint32_t d = sA[aF & 1] + (uint32_t)(rA * ROWB + q4 * 32);
        cp16s(d, p); cp16s(d + 16, p + 8);
        aF++;
    };
    auto fillB1 = [&](int j, int kc) {
        const __half* p = g_W1hT + (size_t)(j * 128 + rA) * K + kc * 64 + q4 * 16;
        uint32_t d = sB[bF & 1] + (uint32_t)(rA * ROWB + q4 * 32);
        cp16s(d, p); cp16s(d + 16, p + 8);
        bF++;
    };
    auto fillB2 = [&](int j, int kc2) {
        const __half* p = g_W2h + (size_t)rA * HID + j * 128 + kc2 * 64 + q4 * 16;
        uint32_t d = sB[bF & 1] + (uint32_t)(rA * ROWB + q4 * 32);
        cp16s(d, p); cp16s(d + 16, p + 8);
        bF++;
    };

    float o_acc[2][4][4];
    #pragma unroll
    for (int i = 0; i < 2; i++)
        #pragma unroll
        for (int j = 0; j < 4; j++)
            #pragma unroll
            for (int c = 0; c < 4; c++) o_acc[i][j][c] = 0.f;

    fillA(0); fillB1(0, 0); CP_COMMIT();

    for (int j = 0; j < 4; j++) {
        float h_acc[2][4][4];
        #pragma unroll
        for (int i = 0; i < 2; i++)
            #pragma unroll
            for (int jj = 0; jj < 4; jj++)
                #pragma unroll
                for (int c = 0; c < 4; c++) h_acc[i][jj][c] = 0.f;

        for (int kc = 0; kc < S1; kc++) {
            CP_WAIT0();
            __syncthreads();
            if (kc + 1 < S1) { fillA(kc + 1); fillB1(j, kc + 1); }
            else             { fillB2(j, 0); }
            CP_COMMIT();
            compute32<ROWB>(h_acc, sA[aU & 1], sB[bU & 1], wm, wn, lane);
            aU++; bU++;
        }

        #pragma unroll
        for (int mi = 0; mi < 2; mi++) {
            int r0 = wm + mi * 16 + g;
            #pragma unroll
            for (int ni = 0; ni < 4; ni++) {
                int c0 = wn + ni * 8 + tg * 2;
                float b0 = sBias1[j * 128 + c0], b1v = sBias1[j * 128 + c0 + 1];
                *(__half2*)((char*)hTile + r0 * ROWH + c0 * 2) =
                    __floats2half2_rn(gelu_exact(h_acc[mi][ni][0] + b0),
                                      gelu_exact(h_acc[mi][ni][1] + b1v));
                *(__half2*)((char*)hTile + (r0 + 8) * ROWH + c0 * 2) =
                    __floats2half2_rn(gelu_exact(h_acc[mi][ni][2] + b0),
                                      gelu_exact(h_acc[mi][ni][3] + b1v));
            }
        }
        __syncthreads();

        for (int kc2 = 0; kc2 < 2; kc2++) {
            CP_WAIT0();
            __syncthreads();
            if (kc2 == 0)      { fillB2(j, 1); CP_COMMIT(); }
            else if (j + 1 < 4){ fillA(0); fillB1(j + 1, 0); CP_COMMIT(); }
            compute32<ROWH>(o_acc, hB + kc2 * 128, sB[bU & 1], wm, wn, lane);
            bU++;
        }
    }

    #pragma unroll
    for (int mi = 0; mi < 2; mi++) {
        int row0 = rowBase + wm + mi * 16 + g;
        #pragma unroll
        for (int ni = 0; ni < 4; ni++) {
            int col = wn + ni * 8 + tg * 2;
            float b0 = sBias2[col], b1v = sBias2[col + 1];
            if (row0 < M) {
                size_t o = (size_t)row0 * D + col;
                float v0 = o_acc[mi][ni][0] + b0 + res[o];
                float v1 = o_acc[mi][ni][1] + b1v + res[o + 1];
                out[o] = v0; out[o + 1] = v1;
                if (out_h) *(__half2*)(out_h + o) = __floats2half2_rn(v0, v1);
            }
            if (row0 + 8 < M) {
                size_t o = (size_t)(row0 + 8) * D + col;
                float v0 = o_acc[mi][ni][2] + b0 + res[o];
                float v1 = o_acc[mi][ni][3] + b1v + res[o + 1];
                out[o] = v0; out[o + 1] = v1;
                if (out_h) *(__half2*)(out_h + o) = __floats2half2_rn(v0, v1);
            }
        }
    }
}

// ---------------- launch -----------------------------------------------------
extern "C" void kernel_launch(void* const* d_in, const int* in_sizes, int n_in,
                              void* d_out, int out_size) {
    const float* nodes = (const float*)d_in[0];
    const float* edges = (const float*)d_in[1];
    const int*   graph = (const int*)  d_in[2];
    const float* nnw   = (const float*)d_in[3];
    const float* nnb   = (const float*)d_in[4];
    const float* enw   = (const float*)d_in[5];
    const float* enb   = (const float*)d_in[6];
    const float* Wn1   = (const float*)d_in[7];
    const float* bn1   = (const float*)d_in[8];
    const float* Wn2   = (const float*)d_in[9];
    const float* bn2   = (const float*)d_in[10];
    const float* We1   = (const float*)d_in[11];
    const float* be1   = (const float*)d_in[12];
    const float* We2   = (const float*)d_in[13];
    const float* be2   = (const float*)d_in[14];

    float* out_nodes = (float*)d_out;
    float* out_edges = out_nodes + (size_t)N_NODES * D;

    cudaFuncSetAttribute(mlp_fused<0, KN>, cudaFuncAttributeMaxDynamicSharedMemorySize, FM_SMEM);
    cudaFuncSetAttribute(mlp_fused<1, KE>, cudaFuncAttributeMaxDynamicSharedMemorySize, FM_SMEM);

    __half* d_no_h;
    cudaGetSymbolAddress((void**)&d_no_h, g_no_h);

    // 1) init (msg + deg); single fused edge pass (red.v4 scatter + mirror + stats + deg)
    init_kernel<<<(N_NODES * D / 4 + 255) / 256, 256>>>();
    edge_fused_kernel<<<ESB, 128>>>(edges, graph);

    // 2) node batchnorm stats (emits nodes_h / msg_h) -> fold W1 + cvt W2 (merged)
    node_stats_partial<<<NSB, KN>>>(nodes);
    stats_finalize<0><<<KN, FINT>>>(KN, NSB, 1.f / N_NODES, nnw, nnb);
    fold_w2cvt_kernel<<<2 + D * HID / 256, 256>>>(KN, Wn1, bn1, Wn2);

    // 3) node MLP (fused; emits no_h mirror)
    {
        dim3 grd(1, (N_NODES + 127) / 128);
        mlp_fused<0, KN><<<grd, 512, FM_SMEM>>>(nullptr, bn2, nodes, out_nodes, d_no_h, N_NODES);
    }

    // 4) edge batchnorm stats: cols 0..255 degree-weighted, cols 256..383 from fused pass
    edge_stats_deg<<<ESB, 256>>>(out_nodes);
    stats_finalize<1><<<KE, FINT>>>(KE, 0, 1.f / N_EDGES, enw, enb);
    fold_w2cvt_kernel<<<2 + D * HID / 256, 256>>>(KE, We1, be1, We2);

    // 5) edge MLP (fused)
    {
        dim3 grd(1, (N_EDGES + 127) / 128);
        mlp_fused<1, KE><<<grd, 512, FM_SMEM>>>(graph, be2, edges, out_edges, nullptr, N_EDGES);
    }
}

// round 17
// speedup vs baseline: 1.7838x; 1.0605x over previous
#include <cuda_runtime.h>
#include <cuda_fp16.h>
#include <math.h>
#include <stdint.h>

#define N_NODES 50000
#define N_EDGES 320000
#define D       128
#define HID     512
#define KN      256
#define KE      384
#define EPSV    1e-5f
#define NSB 2048    // node-stats partial blocks
#define ESB 2048    // edge-stats (deg) partial blocks
#define E2B 8192    // edge-col partial slots (4 per block)
#define FINT 1024   // finalize threads

// ---------------- device scratch (allocation-free: static globals) ----------
__device__ float  g_msg[(size_t)N_NODES * D];           // fp32 scatter target
__device__ __half g_W1hT[(size_t)HID * KE];             // folded W1 [n][k] fp16
__device__ __half g_W2h[(size_t)D * HID];               // W2 [n][k] fp16
__device__ __half g_nodes_h[(size_t)N_NODES * D];       // fp16 mirrors
__device__ __half g_msg_h[(size_t)N_NODES * D];
__device__ __half g_no_h[(size_t)N_NODES * D];          // out_nodes fp16
__device__ __half g_edges_h[(size_t)N_EDGES * D];
__device__ int    g_deg_src[N_NODES];
__device__ int    g_deg_dst[N_NODES];
__device__ float  g_b1p[HID];
__device__ float  g_scale[KE];
__device__ float  g_shift[KE];
__device__ float  g_psum [(size_t)NSB * KN];            // node stats partials
__device__ float  g_psq  [(size_t)NSB * KN];
__device__ float  g_epsum[(size_t)ESB * KE];            // edge deg-weighted partials (cols 0..255)
__device__ float  g_epsq [(size_t)ESB * KE];
__device__ float  g_e2sum[(size_t)E2B * D];             // edge col partials (cols 256..383)
__device__ float  g_e2sq [(size_t)E2B * D];

// ---------------- helpers ------------------------------------------------
__device__ __forceinline__ float gelu_exact(float x) {
    return 0.5f * x * (1.f + erff(x * 0.70710678118654752f));
}
__device__ __forceinline__ uint32_t smem_u32(const void* p) {
    uint32_t a;
    asm("{ .reg .u64 t; cvta.to.shared.u64 t, %1; cvt.u32.u64 %0, t; }" : "=r"(a) : "l"(p));
    return a;
}
__device__ __forceinline__ void cp16s(uint32_t saddr, const void* g) {
    asm volatile("cp.async.cg.shared.global [%0], [%1], 16;" :: "r"(saddr), "l"(g));
}
#define CP_COMMIT() asm volatile("cp.async.commit_group;" ::: "memory")
#define CP_WAIT0()  asm volatile("cp.async.wait_group 0;" ::: "memory")

__device__ __forceinline__ void ldmx4(uint32_t* r, uint32_t addr) {
    asm volatile("ldmatrix.sync.aligned.m8n8.x4.shared.b16 {%0,%1,%2,%3}, [%4];"
        : "=r"(r[0]), "=r"(r[1]), "=r"(r[2]), "=r"(r[3]) : "r"(addr));
}
__device__ __forceinline__ void mma16(float* c, const uint32_t* a, const uint32_t* b) {
    asm volatile(
        "mma.sync.aligned.m16n8k16.row.col.f32.f16.f16.f32 "
        "{%0,%1,%2,%3}, {%4,%5,%6,%7}, {%8,%9}, {%0,%1,%2,%3};"
        : "+f"(c[0]), "+f"(c[1]), "+f"(c[2]), "+f"(c[3])
        : "r"(a[0]), "r"(a[1]), "r"(a[2]), "r"(a[3]), "r"(b[0]), "r"(b[1]));
}
__device__ __forceinline__ void red4(float* gdst, float4 v) {
    asm volatile("red.global.add.v4.f32 [%0], {%1,%2,%3,%4};"
        :: "l"(gdst), "f"(v.x), "f"(v.y), "f"(v.z), "f"(v.w) : "memory");
}

// k-major tiles: 64 halves/row = 128B + 16B pad = 144B stride
#define ROWB 144
#define ATILE (128 * ROWB)       // 18432 B per 64-k chunk
#define BTILE (128 * ROWB)       // 18432 B
// Htile: 128 halves/row = 256B + 16B pad = 272B stride
#define ROWH 272
#define HTILE (128 * ROWH)       // 34816 B

// ---------------- small kernels ----------------------------------------------
__global__ void init_kernel() {
    int i = blockIdx.x * blockDim.x + threadIdx.x;
    if (i < N_NODES * D / 4) ((float4*)g_msg)[i] = make_float4(0.f, 0.f, 0.f, 0.f);
    if (i < N_NODES) { g_deg_src[i] = 0; g_deg_dst[i] = 0; }
}

// ONE pass over edges: vector-red scatter + fp16 mirror + col stats + degree counts.
__global__ void edge_fused_kernel(const float* __restrict__ edges,
                                  const int* __restrict__ graph) {
    int t = threadIdx.x;
    int sub = t >> 5, lane = t & 31;
    int p = blockIdx.x * 4 + sub;
    float4 s = make_float4(0.f, 0.f, 0.f, 0.f);
    float4 q = make_float4(0.f, 0.f, 0.f, 0.f);
    for (int e = blockIdx.x * 4 + sub; e < N_EDGES; e += gridDim.x * 4) {
        int dd = __ldg(&graph[N_EDGES + e]);
        float4 v = *(const float4*)(edges + (size_t)e * D + lane * 4);
        red4(g_msg + (size_t)dd * D + lane * 4, v);
        __half2 h0 = __floats2half2_rn(v.x, v.y);
        __half2 h1 = __floats2half2_rn(v.z, v.w);
        *(uint2*)(g_edges_h + (size_t)e * D + lane * 4) =
            make_uint2(*(uint32_t*)&h0, *(uint32_t*)&h1);
        s.x += v.x; s.y += v.y; s.z += v.z; s.w += v.w;
        q.x += v.x * v.x; q.y += v.y * v.y; q.z += v.z * v.z; q.w += v.w * v.w;
        if (lane == 0) {
            atomicAdd(&g_deg_dst[dd], 1);
            atomicAdd(&g_deg_src[__ldg(&graph[e])], 1);
        }
    }
    int c = lane * 4;
    *(float4*)(g_e2sum + (size_t)p * D + c) = s;
    *(float4*)(g_e2sq  + (size_t)p * D + c) = q;
}

// node stats over [nodes | msg] + write fp16 mirrors
__global__ void node_stats_partial(const float* __restrict__ nodes) {
    int col = threadIdx.x;
    float s = 0.f, q = 0.f;
    for (int r = blockIdx.x; r < N_NODES; r += gridDim.x) {
        float v;
        if (col < D) {
            v = nodes[(size_t)r * D + col];
            g_nodes_h[(size_t)r * D + col] = __float2half_rn(v);
        } else {
            v = g_msg[(size_t)r * D + (col - D)];
            g_msg_h[(size_t)r * D + (col - D)] = __float2half_rn(v);
        }
        s += v; q += v * v;
    }
    g_psum[(size_t)blockIdx.x * KN + col] = s;
    g_psq [(size_t)blockIdx.x * KN + col] = q;
}

// edge-stats cols 0..255 via degree weighting over out_nodes
__global__ void edge_stats_deg(const float* __restrict__ nodesOut) {
    int t = threadIdx.x;
    int c = t & (D - 1);
    float s = 0.f, q = 0.f;
    for (int v = blockIdx.x; v < N_NODES; v += gridDim.x) {
        float x = nodesOut[(size_t)v * D + c];
        float w = (float)((t < D) ? g_deg_src[v] : g_deg_dst[v]);
        s += w * x;
        q += w * x * x;
    }
    g_epsum[(size_t)blockIdx.x * KE + t] = s;
    g_epsq [(size_t)blockIdx.x * KE + t] = q;
}

template <int EDGE>
__global__ void stats_finalize(int ncols, int nparts, float inv_count,
                               const float* __restrict__ w,
                               const float* __restrict__ b) {
    __shared__ float rs[FINT], rq[FINT];
    int col = blockIdx.x;
    int t = threadIdx.x;
    float s = 0.f, q = 0.f;
    if (EDGE) {
        if (col < 2 * D) {
            for (int p = t; p < ESB; p += FINT) {
                s += g_epsum[(size_t)p * KE + col];
                q += g_epsq [(size_t)p * KE + col];
            }
        } else {
            int c2 = col - 2 * D;
            for (int p = t; p < E2B; p += FINT) {
                s += g_e2sum[(size_t)p * D + c2];
                q += g_e2sq [(size_t)p * D + c2];
            }
        }
    } else {
        for (int p = t; p < nparts; p += FINT) {
            s += g_psum[(size_t)p * ncols + col];
            q += g_psq [(size_t)p * ncols + col];
        }
    }
    rs[t] = s; rq[t] = q;
    __syncthreads();
    for (int off = FINT / 2; off > 0; off >>= 1) {
        if (t < off) { rs[t] += rs[t + off]; rq[t] += rq[t + off]; }
        __syncthreads();
    }
    if (t == 0) {
        float mean = rs[0] * inv_count;
        float var  = fmaxf(rq[0] * inv_count - mean * mean, 0.f);
        float sc   = rsqrtf(var + EPSV) * w[col];
        g_scale[col] = sc;
        g_shift[col] = b[col] - mean * sc;
    }
}

// Merged: blocks 0..1 fold BN into W1 (transposed fp16); blocks 2..257 convert W2.
__global__ void fold_w2cvt_kernel(int K, const float* __restrict__ W1,
                                  const float* __restrict__ b1,
                                  const float* __restrict__ W2) {
    if (blockIdx.x < 2) {
        int j = blockIdx.x * 256 + threadIdx.x;
        float acc = b1[j];
        for (int k = 0; k < K; k++) {
            float wv = W1[(size_t)k * HID + j];
            acc += g_shift[k] * wv;
            g_W1hT[(size_t)j * K + k] = __float2half_rn(wv * g_scale[k]);
        }
        g_b1p[j] = acc;
    } else {
        int i = (blockIdx.x - 2) * 256 + threadIdx.x;
        int n = i >> 9, k = i & 511;
        g_W2h[i] = __float2half_rn(W2[(size_t)k * D + n]);
    }
}

// ---------------- warp-tile compute: 32(m) x 32(n) x 64(k) -------------------
template <int ASTR>
__device__ __forceinline__ void compute32(float (&acc)[2][4][4],
                                          uint32_t sA, uint32_t sB,
                                          int wm, int wn, int lane) {
    #pragma unroll
    for (int kk = 0; kk < 64; kk += 16) {
        uint32_t a[2][4];
        #pragma unroll
        for (int mi = 0; mi < 2; mi++) {
            uint32_t addr = sA + (uint32_t)((wm + mi * 16 + (lane & 15)) * ASTR
                                            + kk * 2 + ((lane >> 4) & 1) * 16);
            ldmx4(a[mi], addr);
        }
        uint32_t b[2][4];
        #pragma unroll
        for (int nt = 0; nt < 2; nt++) {
            int nr = wn + nt * 16 + (lane & 7) + ((lane >> 4) & 1) * 8;
            int kof = kk + ((lane >> 3) & 1) * 8;
            ldmx4(b[nt], sB + (uint32_t)(nr * ROWB + kof * 2));
        }
        #pragma unroll
        for (int mi = 0; mi < 2; mi++)
            #pragma unroll
            for (int nt = 0; nt < 2; nt++) {
                mma16(acc[mi][nt * 2 + 0], a[mi], &b[nt][0]);
                mma16(acc[mi][nt * 2 + 1], a[mi], &b[nt][2]);
            }
    }
}

// ---------------- FUSED MLP: out = (gelu(X@W1+b1))@W2 + b2 + res -------------
// A tile persists in smem across all 4 hidden chunks: loaded once during j=0
// (same per-chunk prefetch schedule), reused for j=1..3. Kills the 3x A re-read
// (720 MB of random gathers on the edge pass).
#define FM_SMEM(K) ((K / 64) * ATILE + 2 * BTILE + HTILE + 2048 + 512 + 64)

template <int MODE, int K>
__global__ __launch_bounds__(512)
void mlp_fused(const int* __restrict__ graph,
               const float* __restrict__ b2,
               const float* __restrict__ res,
               float* __restrict__ out,
               __half* __restrict__ out_h,
               int M) {
    constexpr int S1 = K / 64;
    extern __shared__ __align__(16) char smem[];
    uint32_t base = smem_u32(smem);
    // A: S1 persistent chunks; then B double buffer; then Htile; then biases.
    uint32_t sB[2] = { base + S1 * ATILE, base + S1 * ATILE + BTILE };
    uint32_t hB    = base + S1 * ATILE + 2 * BTILE;
    float* sBias1 = (float*)(smem + S1 * ATILE + 2 * BTILE + HTILE);
    float* sBias2 = (float*)(smem + S1 * ATILE + 2 * BTILE + HTILE + 2048);
    __half* hTile = (__half*)(smem + S1 * ATILE + 2 * BTILE);

    const int tid = threadIdx.x, lane = tid & 31, wid = tid >> 5;
    const int wm = (wid & 3) * 32, wn = (wid >> 2) * 32;
    const int rowBase = blockIdx.y * 128;
    const int g = lane >> 2, tg = lane & 3;

    for (int i = tid; i < HID; i += 512) sBias1[i] = g_b1p[i];
    if (tid < 128) sBias2[tid] = b2[tid];

    const int rA = tid >> 2, q4 = tid & 3;
    const int mA = rowBase + rA;
    const int mc = (mA < M) ? mA : (M - 1);
    int vsrc = 0, vdst = 0;
    if (MODE == 1) { vsrc = graph[mc]; vdst = graph[N_EDGES + mc]; }

    int bF = 0, bU = 0;

    auto fillA = [&](int kc) {   // -> persistent chunk kc
        int khalf = kc * 64 + q4 * 16;
        int seg = khalf >> 7, l = khalf & 127;
        const __half* p;
        if (MODE == 0) {
            p = (seg == 0 ? g_nodes_h + (size_t)mc * D : g_msg_h + (size_t)mc * D) + l;
        } else {
            p = (seg == 0 ? g_no_h + (size_t)vsrc * D
               : seg == 1 ? g_no_h + (size_t)vdst * D
                          : g_edges_h + (size_t)mc * D) + l;
        }
        uint32_t d = base + kc * ATILE + (uint32_t)(rA * ROWB + q4 * 32);
        cp16s(d, p); cp16s(d + 16, p + 8);
    };
    auto fillB1 = [&](int j, int kc) {
        const __half* p = g_W1hT + (size_t)(j * 128 + rA) * K + kc * 64 + q4 * 16;
        uint32_t d = sB[bF & 1] + (uint32_t)(rA * ROWB + q4 * 32);
        cp16s(d, p); cp16s(d + 16, p + 8);
        bF++;
    };
    auto fillB2 = [&](int j, int kc2) {
        const __half* p = g_W2h + (size_t)rA * HID + j * 128 + kc2 * 64 + q4 * 16;
        uint32_t d = sB[bF & 1] + (uint32_t)(rA * ROWB + q4 * 32);
        cp16s(d, p); cp16s(d + 16, p + 8);
        bF++;
    };

    float o_acc[2][4][4];
    #pragma unroll
    for (int i = 0; i < 2; i++)
        #pragma unroll
        for (int j = 0; j < 4; j++)
            #pragma unroll
            for (int c = 0; c < 4; c++) o_acc[i][j][c] = 0.f;

    fillA(0); fillB1(0, 0); CP_COMMIT();

    for (int j = 0; j < 4; j++) {
        float h_acc[2][4][4];
        #pragma unroll
        for (int i = 0; i < 2; i++)
            #pragma unroll
            for (int jj = 0; jj < 4; jj++)
                #pragma unroll
                for (int c = 0; c < 4; c++) h_acc[i][jj][c] = 0.f;

        // ---- stage 1: h_acc = X @ W1[:, j*128 .. +128] ----
        for (int kc = 0; kc < S1; kc++) {
            CP_WAIT0();
            __syncthreads();
            if (kc + 1 < S1) {
                if (j == 0) fillA(kc + 1);   // A loaded once, during j=0 only
                fillB1(j, kc + 1);
            } else {
                fillB2(j, 0);
            }
            CP_COMMIT();
            compute32<ROWB>(h_acc, base + kc * ATILE, sB[bU & 1], wm, wn, lane);
            bU++;
        }

        // ---- stage-1 epilogue: bias + gelu -> Htile (smem) ----
        #pragma unroll
        for (int mi = 0; mi < 2; mi++) {
            int r0 = wm + mi * 16 + g;
            #pragma unroll
            for (int ni = 0; ni < 4; ni++) {
                int c0 = wn + ni * 8 + tg * 2;
                float b0 = sBias1[j * 128 + c0], b1v = sBias1[j * 128 + c0 + 1];
                *(__half2*)((char*)hTile + r0 * ROWH + c0 * 2) =
                    __floats2half2_rn(gelu_exact(h_acc[mi][ni][0] + b0),
                                      gelu_exact(h_acc[mi][ni][1] + b1v));
                *(__half2*)((char*)hTile + (r0 + 8) * ROWH + c0 * 2) =
                    __floats2half2_rn(gelu_exact(h_acc[mi][ni][2] + b0),
                                      gelu_exact(h_acc[mi][ni][3] + b1v));
            }
        }
        __syncthreads();

        // ---- stage 2: o_acc += Htile @ W2[j-chunk] ----
        for (int kc2 = 0; kc2 < 2; kc2++) {
            CP_WAIT0();
            __syncthreads();
            if (kc2 == 0)       { fillB2(j, 1); CP_COMMIT(); }
            else if (j + 1 < 4) { fillB1(j + 1, 0); CP_COMMIT(); }
            compute32<ROWH>(o_acc, hB + kc2 * 128, sB[bU & 1], wm, wn, lane);
            bU++;
        }
    }

    // ---- final epilogue: out = o_acc + b2 + res (+ fp16 mirror) ----
    #pragma unroll
    for (int mi = 0; mi < 2; mi++) {
        int row0 = rowBase + wm + mi * 16 + g;
        #pragma unroll
        for (int ni = 0; ni < 4; ni++) {
            int col = wn + ni * 8 + tg * 2;
            float b0 = sBias2[col], b1v = sBias2[col + 1];
            if (row0 < M) {
                size_t o = (size_t)row0 * D + col;
                float v0 = o_acc[mi][ni][0] + b0 + res[o];
                float v1 = o_acc[mi][ni][1] + b1v + res[o + 1];
                out[o] = v0; out[o + 1] = v1;
                if (out_h) *(__half2*)(out_h + o) = __floats2half2_rn(v0, v1);
            }
            if (row0 + 8 < M) {
                size_t o = (size_t)(row0 + 8) * D + col;
                float v0 = o_acc[mi][ni][2] + b0 + res[o];
                float v1 = o_acc[mi][ni][3] + b1v + res[o + 1];
                out[o] = v0; out[o + 1] = v1;
                if (out_h) *(__half2*)(out_h + o) = __floats2half2_rn(v0, v1);
            }
        }
    }
}

// ---------------- launch -----------------------------------------------------
extern "C" void kernel_launch(void* const* d_in, const int* in_sizes, int n_in,
                              void* d_out, int out_size) {
    const float* nodes = (const float*)d_in[0];
    const float* edges = (const float*)d_in[1];
    const int*   graph = (const int*)  d_in[2];
    const float* nnw   = (const float*)d_in[3];
    const float* nnb   = (const float*)d_in[4];
    const float* enw   = (const float*)d_in[5];
    const float* enb   = (const float*)d_in[6];
    const float* Wn1   = (const float*)d_in[7];
    const float* bn1   = (const float*)d_in[8];
    const float* Wn2   = (const float*)d_in[9];
    const float* bn2   = (const float*)d_in[10];
    const float* We1   = (const float*)d_in[11];
    const float* be1   = (const float*)d_in[12];
    const float* We2   = (const float*)d_in[13];
    const float* be2   = (const float*)d_in[14];

    float* out_nodes = (float*)d_out;
    float* out_edges = out_nodes + (size_t)N_NODES * D;

    cudaFuncSetAttribute(mlp_fused<0, KN>, cudaFuncAttributeMaxDynamicSharedMemorySize, FM_SMEM(KN));
    cudaFuncSetAttribute(mlp_fused<1, KE>, cudaFuncAttributeMaxDynamicSharedMemorySize, FM_SMEM(KE));

    __half* d_no_h;
    cudaGetSymbolAddress((void**)&d_no_h, g_no_h);

    // 1) init (msg + deg); single fused edge pass (red.v4 scatter + mirror + stats + deg)
    init_kernel<<<(N_NODES * D / 4 + 255) / 256, 256>>>();
    edge_fused_kernel<<<ESB, 128>>>(edges, graph);

    // 2) node batchnorm stats (emits nodes_h / msg_h) -> fold W1 + cvt W2 (merged)
    node_stats_partial<<<NSB, KN>>>(nodes);
    stats_finalize<0><<<KN, FINT>>>(KN, NSB, 1.f / N_NODES, nnw, nnb);
    fold_w2cvt_kernel<<<2 + D * HID / 256, 256>>>(KN, Wn1, bn1, Wn2);

    // 3) node MLP (fused; emits no_h mirror)
    {
        dim3 grd(1, (N_NODES + 127) / 128);
        mlp_fused<0, KN><<<grd, 512, FM_SMEM(KN)>>>(nullptr, bn2, nodes, out_nodes, d_no_h, N_NODES);
    }

    // 4) edge batchnorm stats: cols 0..255 degree-weighted, cols 256..383 from fused pass
    edge_stats_deg<<<ESB, 256>>>(out_nodes);
    stats_finalize<1><<<KE, FINT>>>(KE, 0, 1.f / N_EDGES, enw, enb);
    fold_w2cvt_kernel<<<2 + D * HID / 256, 256>>>(KE, We1, be1, We2);

    // 5) edge MLP (fused)
    {
        dim3 grd(1, (N_EDGES + 127) / 128);
        mlp_fused<1, KE><<<grd, 512, FM_SMEM(KE)>>>(graph, be2, edges, out_edges, nullptr, N_EDGES);
    }
}